// round 1
// baseline (speedup 1.0000x reference)
#include <cuda_runtime.h>
#include <math.h>

// Problem constants
#define Bb 32
#define Tt 2048
#define Cc 1024
#define Hh 64
#define BT (Bb * Tt)

// Scratch (allocation-free rule: __device__ globals)
__device__ float g_q[(size_t)BT * Hh];                 // [b*T + t][h], pre-scaled by 1/8
__device__ float g_kT[(size_t)Bb * Hh * Tt];           // [b][h][t]  (transposed per batch)
__device__ float g_v[(size_t)BT * Hh];                 // [b*T + t][h]

// ---------------------------------------------------------------------------
// Projection kernel: one block computes a 64-row x 192-col tile of
// [x @ (Wk|Wq|Wv)]. Register microtile 8x6 per thread (256 threads).
// K is written transposed ([b][h][t]); Q is scaled by H^-0.5 = 0.125.
// ---------------------------------------------------------------------------
__global__ __launch_bounds__(256) void proj_kernel(
    const float* __restrict__ x,
    const float* __restrict__ Wk,
    const float* __restrict__ Wq,
    const float* __restrict__ Wv)
{
    __shared__ float sx[64 * 32];   // x tile  [64 rows][32 k]
    __shared__ float sw[32 * 192];  // W tile  [32 k][192 cols: k|q|v]

    const int tid  = threadIdx.x;
    const int row0 = blockIdx.x * 64;
    const int tr   = tid >> 5;        // 0..7  (row group)
    const int tc   = tid & 31;        // 0..31 (col lane)

    float acc[8][6];
#pragma unroll
    for (int i = 0; i < 8; i++)
#pragma unroll
        for (int j = 0; j < 6; j++) acc[i][j] = 0.f;

    const int xr  = tid >> 3;          // 0..31
    const int xc4 = (tid & 7) * 4;     // 0..28
    const int wr  = tid >> 4;          // 0..15
    const int wc4 = (tid & 15) * 4;    // 0..60

    for (int c0 = 0; c0 < Cc; c0 += 32) {
        __syncthreads();
        // load x tile 64x32 (float4, coalesced)
#pragma unroll
        for (int rr = xr; rr < 64; rr += 32) {
            *(float4*)&sx[rr * 32 + xc4] =
                *(const float4*)&x[(size_t)(row0 + rr) * Cc + c0 + xc4];
        }
        // load W tiles 32x64 each into combined [32][192]
#pragma unroll
        for (int rr = wr; rr < 32; rr += 16) {
            *(float4*)&sw[rr * 192 +       wc4] = *(const float4*)&Wk[(size_t)(c0 + rr) * Hh + wc4];
            *(float4*)&sw[rr * 192 +  64 + wc4] = *(const float4*)&Wq[(size_t)(c0 + rr) * Hh + wc4];
            *(float4*)&sw[rr * 192 + 128 + wc4] = *(const float4*)&Wv[(size_t)(c0 + rr) * Hh + wc4];
        }
        __syncthreads();

#pragma unroll 4
        for (int kk = 0; kk < 32; kk++) {
            float xf[8], wf[6];
#pragma unroll
            for (int i = 0; i < 8; i++) xf[i] = sx[(tr * 8 + i) * 32 + kk];   // broadcast
#pragma unroll
            for (int j = 0; j < 6; j++) wf[j] = sw[kk * 192 + tc + 32 * j];   // conflict-free
#pragma unroll
            for (int i = 0; i < 8; i++)
#pragma unroll
                for (int j = 0; j < 6; j++) acc[i][j] = fmaf(xf[i], wf[j], acc[i][j]);
        }
    }

    // epilogue: route columns to k (transposed), q (scaled), v
#pragma unroll
    for (int i = 0; i < 8; i++) {
        const int r = row0 + tr * 8 + i;
        const int b = r >> 11;        // / 2048
        const int t = r & 2047;
#pragma unroll
        for (int j = 0; j < 6; j++) {
            const int col = tc + 32 * j;
            const float val = acc[i][j];
            if (col < 64) {
                g_kT[((size_t)b * Hh + col) * Tt + t] = val;          // transposed scatter
            } else if (col < 128) {
                g_q[(size_t)r * Hh + (col - 64)] = val * 0.125f;      // fold 1/sqrt(H)
            } else {
                g_v[(size_t)r * Hh + (col - 128)] = val;
            }
        }
    }
}

// ---------------------------------------------------------------------------
// Flash-attention kernel (causal): one block per (batch, 64-row q tile).
// 256 threads, 4x4 microtiles (16x16 thread grid). Online softmax with
// width-16 shuffle reductions. P is staged through the K smem buffer.
// smem = 3 * 64*64 * 4B = 49152 bytes (dynamic, within default 48KB limit).
// ---------------------------------------------------------------------------
__global__ __launch_bounds__(256) void attn_kernel(float* __restrict__ out)
{
    extern __shared__ float sm[];
    float* sq  = sm;                 // [64][64]  q rows x h
    float* skp = sm + 64 * 64;       // S-phase: kT [h][t'];  O-phase: P [qr][kc]
    float* sv  = sm + 2 * 64 * 64;   // [t'][h]

    const int tid = threadIdx.x;
    const int b   = blockIdx.y;
    const int qt  = blockIdx.x;
    const int q0  = qt * 64;

    const int tr  = tid >> 4;        // 0..15 (q-row group / also loader row)
    const int tc  = tid & 15;        // 0..15 (col group)
    const int lc4 = tc * 4;          // 0..60 (loader col, float4)

    // load q tile
    {
        const float* qb = g_q + ((size_t)b * Tt + q0) * Hh;
#pragma unroll
        for (int rr = tr; rr < 64; rr += 16)
            *(float4*)&sq[rr * 64 + lc4] = *(const float4*)&qb[rr * Hh + lc4];
    }

    float o[4][4];
    float m[4], l[4];
#pragma unroll
    for (int i = 0; i < 4; i++) {
        m[i] = -1e30f;
        l[i] = 0.f;
#pragma unroll
        for (int j = 0; j < 4; j++) o[i][j] = 0.f;
    }

    const float* kTb = g_kT + (size_t)b * Hh * Tt;
    const float* vb0 = g_v  + (size_t)b * Tt * Hh;

    for (int jt = 0; jt <= qt; jt++) {
        const int j0 = jt * 64;
        __syncthreads();   // previous O-phase (and q-load) complete before overwrite
        // load kT tile [h=0..63][t'=0..63] and v tile [t'][h]
#pragma unroll
        for (int rr = tr; rr < 64; rr += 16) {
            *(float4*)&skp[rr * 64 + lc4] = *(const float4*)&kTb[(size_t)rr * Tt + j0 + lc4];
            *(float4*)&sv [rr * 64 + lc4] = *(const float4*)&vb0[(size_t)(j0 + rr) * Hh + lc4];
        }
        __syncthreads();

        // ---- S = q @ kT (4x4 per thread) ----
        float s[4][4];
#pragma unroll
        for (int i = 0; i < 4; i++)
#pragma unroll
            for (int j = 0; j < 4; j++) s[i][j] = 0.f;

#pragma unroll 4
        for (int h4 = 0; h4 < 64; h4 += 4) {
            float qf[4][4];
#pragma unroll
            for (int i = 0; i < 4; i++)
                *(float4*)qf[i] = *(const float4*)&sq[(tr * 4 + i) * 64 + h4];   // broadcast
#pragma unroll
            for (int hh = 0; hh < 4; hh++) {
                float kf[4];
                *(float4*)kf = *(const float4*)&skp[(h4 + hh) * 64 + tc * 4];    // conflict-free
#pragma unroll
                for (int i = 0; i < 4; i++)
#pragma unroll
                    for (int j = 0; j < 4; j++)
                        s[i][j] = fmaf(qf[i][hh], kf[j], s[i][j]);
            }
        }

        // causal mask on the diagonal tile (q0 == j0)
        if (jt == qt) {
#pragma unroll
            for (int i = 0; i < 4; i++)
#pragma unroll
                for (int j = 0; j < 4; j++)
                    if (tc * 4 + j > tr * 4 + i) s[i][j] = -1e30f;
        }

        // ---- online softmax (row reductions across the 16 tc lanes) ----
#pragma unroll
        for (int i = 0; i < 4; i++) {
            float mx = fmaxf(fmaxf(s[i][0], s[i][1]), fmaxf(s[i][2], s[i][3]));
#pragma unroll
            for (int off = 8; off > 0; off >>= 1)
                mx = fmaxf(mx, __shfl_xor_sync(0xffffffffu, mx, off, 16));
            const float mn = fmaxf(m[i], mx);
            const float alpha = __expf(m[i] - mn);
            float sum = 0.f;
#pragma unroll
            for (int j = 0; j < 4; j++) {
                s[i][j] = __expf(s[i][j] - mn);
                sum += s[i][j];
            }
#pragma unroll
            for (int off = 8; off > 0; off >>= 1)
                sum += __shfl_xor_sync(0xffffffffu, sum, off, 16);
            l[i] = l[i] * alpha + sum;
            m[i] = mn;
#pragma unroll
            for (int j = 0; j < 4; j++) o[i][j] *= alpha;
        }

        __syncthreads();   // everyone done reading kT from skp
        // stage P into skp as [qrow][kcol]
#pragma unroll
        for (int i = 0; i < 4; i++) {
            float4 p4 = make_float4(s[i][0], s[i][1], s[i][2], s[i][3]);
            *(float4*)&skp[(tr * 4 + i) * 64 + tc * 4] = p4;
        }
        __syncthreads();

        // ---- O += P @ V (4x4 per thread) ----
#pragma unroll 4
        for (int j4 = 0; j4 < 64; j4 += 4) {
            float pf[4][4];
#pragma unroll
            for (int i = 0; i < 4; i++)
                *(float4*)pf[i] = *(const float4*)&skp[(tr * 4 + i) * 64 + j4]; // broadcast
#pragma unroll
            for (int jj = 0; jj < 4; jj++) {
                float vf[4];
                *(float4*)vf = *(const float4*)&sv[(j4 + jj) * 64 + tc * 4];    // conflict-free
#pragma unroll
                for (int i = 0; i < 4; i++)
#pragma unroll
                    for (int j = 0; j < 4; j++)
                        o[i][j] = fmaf(pf[i][jj], vf[j], o[i][j]);
            }
        }
    }

    // normalize + write out (coalesced float4)
    float* ob = out + ((size_t)b * Tt + q0) * Hh;
#pragma unroll
    for (int i = 0; i < 4; i++) {
        const float inv = 1.f / l[i];
        float4 r4 = make_float4(o[i][0] * inv, o[i][1] * inv, o[i][2] * inv, o[i][3] * inv);
        *(float4*)&ob[(tr * 4 + i) * Hh + tc * 4] = r4;
    }
}

// ---------------------------------------------------------------------------
// Harness entry
// ---------------------------------------------------------------------------
extern "C" void kernel_launch(void* const* d_in, const int* in_sizes, int n_in,
                              void* d_out, int out_size)
{
    const float* x  = (const float*)d_in[0];
    const float* Wk = (const float*)d_in[1];
    const float* Wq = (const float*)d_in[2];
    const float* Wv = (const float*)d_in[3];
    float* out = (float*)d_out;

    proj_kernel<<<BT / 64, 256>>>(x, Wk, Wq, Wv);
    attn_kernel<<<dim3(Tt / 64, Bb), 256, 3 * 64 * 64 * sizeof(float)>>>(out);
}

// round 3
// speedup vs baseline: 1.3780x; 1.3780x over previous
#include <cuda_runtime.h>
#include <cuda_bf16.h>
#include <mma.h>
#include <cstdint>

using namespace nvcuda;

// Problem constants
#define Bb 32
#define Tt 2048
#define Cc 1024
#define Hh 64
#define BT (Bb * Tt)

// 0.125 (= H^-0.5) * log2(e): scores computed directly in base-2 domain
#define QSCALE 0.180336880111227f

// Scratch (__device__ globals; no allocation allowed)
__device__ __nv_bfloat16 g_Whi[(size_t)Cc * 192];    // [k][n]  n: 0..63 K, 64..127 Q, 128..191 V
__device__ __nv_bfloat16 g_Wlo[(size_t)Cc * 192];
__device__ __nv_bfloat16 g_qhi[(size_t)BT * Hh], g_qlo[(size_t)BT * Hh];
__device__ __nv_bfloat16 g_khi[(size_t)BT * Hh], g_klo[(size_t)BT * Hh];
__device__ __nv_bfloat16 g_vhi[(size_t)BT * Hh], g_vlo[(size_t)BT * Hh];

// ---------------------------------------------------------------------------
// Fast 2^x on the FMA pipe (x in [-125, 0]); rel err ~2.4e-6
// ---------------------------------------------------------------------------
__device__ __forceinline__ float fexp2(float x) {
    float z = x + 12582912.f;                 // round x to nearest int in mantissa
    float r = x - (z - 12582912.f);           // r in [-0.5, 0.5]
    int   e = __float_as_int(z) << 23;        // integer part -> exponent bits
    float p = 1.3333558146428443e-3f;
    p = fmaf(p, r, 9.6181291076284770e-3f);
    p = fmaf(p, r, 5.5504108664821580e-2f);
    p = fmaf(p, r, 2.4022650695910071e-1f);
    p = fmaf(p, r, 6.9314718055994531e-1f);
    p = fmaf(p, r, 1.0f);
    return __int_as_float(__float_as_int(p) + e);
}

__device__ __forceinline__ void split2(float a, float b, uint32_t& h, uint32_t& l) {
    __nv_bfloat162 hv, lv;
    hv.x = __float2bfloat16(a); hv.y = __float2bfloat16(b);
    lv.x = __float2bfloat16(a - __bfloat162float(hv.x));
    lv.y = __float2bfloat16(b - __bfloat162float(hv.y));
    h = *(uint32_t*)&hv; l = *(uint32_t*)&lv;
}

// ---------------------------------------------------------------------------
// Prep: split W (with Q scale folded) into bf16 hi/lo, layout [k=1024][n=192]
// ---------------------------------------------------------------------------
__global__ __launch_bounds__(256) void prep_w(
    const float* __restrict__ Wk, const float* __restrict__ Wq, const float* __restrict__ Wv)
{
    const int idx = blockIdx.x * 256 + threadIdx.x;   // < 196608
    const int k = idx / 192, n = idx % 192;
    float f;
    if (n < 64)       f = Wk[k * 64 + n];
    else if (n < 128) f = Wq[k * 64 + (n - 64)] * QSCALE;
    else              f = Wv[k * 64 + (n - 128)];
    __nv_bfloat16 hi = __float2bfloat16(f);
    g_Whi[idx] = hi;
    g_Wlo[idx] = __float2bfloat16(f - __bfloat162float(hi));
}

// ---------------------------------------------------------------------------
// Projection GEMM (wmma bf16, 3-term hi/lo): CTA = 128 rows x 192 cols, K=1024
// 8 warps: warp_m in 0..3 (32 rows), warp_n in 0..1 (96 cols)
// ---------------------------------------------------------------------------
#define PA_LD 80     // A smem ldm (bf16 elems), 160B rows
#define PB_LD 208    // B smem ldm, 416B rows
#define PC_LD 104    // epilogue fp32 ldm, 416B rows
#define PJ_A_HI 0
#define PJ_A_LO 20480
#define PJ_B_HI 40960
#define PJ_B_LO 67584
#define PJ_SMEM 94208

__global__ __launch_bounds__(256) void proj_tc(const float* __restrict__ x)
{
    extern __shared__ char smp[];
    __nv_bfloat16* sAh = (__nv_bfloat16*)(smp + PJ_A_HI);
    __nv_bfloat16* sAl = (__nv_bfloat16*)(smp + PJ_A_LO);
    __nv_bfloat16* sBh = (__nv_bfloat16*)(smp + PJ_B_HI);
    __nv_bfloat16* sBl = (__nv_bfloat16*)(smp + PJ_B_LO);
    float* sC = (float*)smp;   // epilogue overlay (53248B <= 94208B)

    const int tid = threadIdx.x;
    const int wid = tid >> 5;
    const int wm  = wid >> 1;        // 0..3
    const int wn  = wid & 1;         // 0..1
    const int row0 = blockIdx.x * 128;

    wmma::fragment<wmma::accumulator, 16, 16, 16, float> c[2][6];
#pragma unroll
    for (int mi = 0; mi < 2; mi++)
#pragma unroll
        for (int ni = 0; ni < 6; ni++) wmma::fill_fragment(c[mi][ni], 0.f);

    const int ar = tid >> 1, ah_ = tid & 1;       // A loader: row, col-half

    for (int s = 0; s < 16; s++) {
        const int c0 = s * 64;
        __syncthreads();
        // ---- A: x fp32 -> bf16 hi/lo, [128][64] ----
        {
            const float* src = x + (size_t)(row0 + ar) * Cc + c0 + ah_ * 32;
            char* dh = (char*)sAh + ar * (PA_LD * 2) + ah_ * 64;
            char* dl = (char*)sAl + ar * (PA_LD * 2) + ah_ * 64;
#pragma unroll
            for (int i = 0; i < 8; i++) {
                float4 f = ((const float4*)src)[i];
                uint2 hv, lv;
                split2(f.x, f.y, hv.x, lv.x);
                split2(f.z, f.w, hv.y, lv.y);
                *(uint2*)(dh + i * 8) = hv;
                *(uint2*)(dl + i * 8) = lv;
            }
        }
        // ---- B: g_Whi/g_Wlo [64][192] ----
#pragma unroll
        for (int i = 0; i < 6; i++) {
            const int idx = i * 256 + tid;            // < 1536
            const int r = idx / 24, cg = idx % 24;    // 24 uint4 per 192-col row
            const size_t gsrc = (size_t)(c0 + r) * 192;
            *((uint4*)((char*)sBh + r * (PB_LD * 2)) + cg) = *((const uint4*)(g_Whi + gsrc) + cg);
            *((uint4*)((char*)sBl + r * (PB_LD * 2)) + cg) = *((const uint4*)(g_Wlo + gsrc) + cg);
        }
        __syncthreads();

        // ---- MMA: 4 k16 steps x (2m x 6n) x 3 terms ----
#pragma unroll
        for (int ks = 0; ks < 4; ks++) {
            wmma::fragment<wmma::matrix_a, 16, 16, 16, __nv_bfloat16, wmma::row_major> fah[2], fal[2];
#pragma unroll
            for (int mi = 0; mi < 2; mi++) {
                const int ro = (wm * 32 + mi * 16) * PA_LD + ks * 16;
                wmma::load_matrix_sync(fah[mi], sAh + ro, PA_LD);
                wmma::load_matrix_sync(fal[mi], sAl + ro, PA_LD);
            }
#pragma unroll
            for (int ni = 0; ni < 6; ni++) {
                wmma::fragment<wmma::matrix_b, 16, 16, 16, __nv_bfloat16, wmma::row_major> fbh, fbl;
                const int bo = ks * 16 * PB_LD + wn * 96 + ni * 16;
                wmma::load_matrix_sync(fbh, sBh + bo, PB_LD);
                wmma::load_matrix_sync(fbl, sBl + bo, PB_LD);
#pragma unroll
                for (int mi = 0; mi < 2; mi++) {
                    wmma::mma_sync(c[mi][ni], fah[mi], fbh, c[mi][ni]);
                    wmma::mma_sync(c[mi][ni], fah[mi], fbl, c[mi][ni]);
                    wmma::mma_sync(c[mi][ni], fal[mi], fbh, c[mi][ni]);
                }
            }
        }
    }

    // ---- epilogue: two 96-col passes through smem, write bf16 hi/lo ----
    for (int pass = 0; pass < 2; pass++) {
        __syncthreads();
        if (wn == pass) {
#pragma unroll
            for (int mi = 0; mi < 2; mi++)
#pragma unroll
                for (int ni = 0; ni < 6; ni++)
                    wmma::store_matrix_sync(sC + (wm * 32 + mi * 16) * PC_LD + ni * 16,
                                            c[mi][ni], PC_LD, wmma::mem_row_major);
        }
        __syncthreads();
        const int r = tid >> 1, hf = tid & 1;
        const size_t gr = (size_t)(row0 + r) * Hh;
        const float* src = sC + r * PC_LD + hf * 48;
#pragma unroll
        for (int j = 0; j < 48; j += 2) {
            const int col = pass * 96 + hf * 48 + j;
            uint32_t hp, lp;
            split2(src[j], src[j + 1], hp, lp);
            __nv_bfloat16 *dh, *dl; int cc;
            if (col < 64)       { dh = g_khi; dl = g_klo; cc = col; }
            else if (col < 128) { dh = g_qhi; dl = g_qlo; cc = col - 64; }
            else                { dh = g_vhi; dl = g_vlo; cc = col - 128; }
            *(uint32_t*)(dh + gr + cc) = hp;
            *(uint32_t*)(dl + gr + cc) = lp;
        }
    }
}

// ---------------------------------------------------------------------------
// Flash attention (wmma bf16 3-term + FMA exp2): CTA = 64 q-rows, 4 warps
// ---------------------------------------------------------------------------
#define ALD 80     // bf16 ldm (160B rows)
#define SLD 104    // fp32 ldm (416B rows)
#define AT_QH 0
#define AT_QL 10240
#define AT_KH 20480
#define AT_KL 30720
#define AT_VH 40960
#define AT_VL 51200
#define AT_SP 61440
#define AT_PH 88064
#define AT_PL 98304
#define AT_SMEM 108544

__global__ __launch_bounds__(128) void attn_tc(float* __restrict__ out)
{
    extern __shared__ char sma[];
    __nv_bfloat16* sQh = (__nv_bfloat16*)(sma + AT_QH);
    __nv_bfloat16* sQl = (__nv_bfloat16*)(sma + AT_QL);
    __nv_bfloat16* sKh = (__nv_bfloat16*)(sma + AT_KH);
    __nv_bfloat16* sKl = (__nv_bfloat16*)(sma + AT_KL);
    __nv_bfloat16* sVh = (__nv_bfloat16*)(sma + AT_VH);
    __nv_bfloat16* sVl = (__nv_bfloat16*)(sma + AT_VL);
    float*         sSP = (float*)(sma + AT_SP);
    __nv_bfloat16* sPh = (__nv_bfloat16*)(sma + AT_PH);
    __nv_bfloat16* sPl = (__nv_bfloat16*)(sma + AT_PL);

    const int tid  = threadIdx.x;
    const int wid  = tid >> 5;
    const int lane = tid & 31;
    const int b    = blockIdx.y;
    const int qt   = (gridDim.x - 1) - blockIdx.x;   // big tiles scheduled first
    const int q0   = qt * 64;

    // load Q hi/lo tile [64 tok][64 h]
#pragma unroll
    for (int i = 0; i < 4; i++) {
        const int idx = i * 128 + tid;               // < 512
        const int r = idx >> 3, cg = idx & 7;
        const size_t g = (size_t)(b * Tt + q0 + r) * Hh;
        *((uint4*)((char*)sQh + r * (ALD * 2)) + cg) = *((const uint4*)(g_qhi + g) + cg);
        *((uint4*)((char*)sQl + r * (ALD * 2)) + cg) = *((const uint4*)(g_qlo + g) + cg);
    }

    const int rl = (wid << 4) + (lane >> 1);         // owned S row (0..63)
    const int ch = lane & 1;                         // col half (32 cols)

    float O[32];
#pragma unroll
    for (int j = 0; j < 32; j++) O[j] = 0.f;
    float m = -1e30f, l = 0.f;

    const float* srow = sSP + rl * SLD + ch * 32;

    for (int jt = 0; jt <= qt; jt++) {
        const int j0 = jt * 64;
        __syncthreads();   // prior tile's K/V readers done (covers Q-load on iter 0)
        // load K,V hi/lo tiles [64 tok][64 h]
#pragma unroll
        for (int i = 0; i < 4; i++) {
            const int idx = i * 128 + tid;
            const int r = idx >> 3, cg = idx & 7;
            const size_t g = (size_t)(b * Tt + j0 + r) * Hh;
            *((uint4*)((char*)sKh + r * (ALD * 2)) + cg) = *((const uint4*)(g_khi + g) + cg);
            *((uint4*)((char*)sKl + r * (ALD * 2)) + cg) = *((const uint4*)(g_klo + g) + cg);
            *((uint4*)((char*)sVh + r * (ALD * 2)) + cg) = *((const uint4*)(g_vhi + g) + cg);
            *((uint4*)((char*)sVl + r * (ALD * 2)) + cg) = *((const uint4*)(g_vlo + g) + cg);
        }
        __syncthreads();

        // ---- S = Q @ K^T  (warp band: rows 16*wid..) ----
        wmma::fragment<wmma::accumulator, 16, 16, 16, float> cs[4];
#pragma unroll
        for (int nf = 0; nf < 4; nf++) wmma::fill_fragment(cs[nf], 0.f);
#pragma unroll
        for (int ks = 0; ks < 4; ks++) {
            wmma::fragment<wmma::matrix_a, 16, 16, 16, __nv_bfloat16, wmma::row_major> fah, fal;
            const int ao = (wid * 16) * ALD + ks * 16;
            wmma::load_matrix_sync(fah, sQh + ao, ALD);
            wmma::load_matrix_sync(fal, sQl + ao, ALD);
#pragma unroll
            for (int nf = 0; nf < 4; nf++) {
                wmma::fragment<wmma::matrix_b, 16, 16, 16, __nv_bfloat16, wmma::col_major> fbh, fbl;
                const int bo = (nf * 16) * ALD + ks * 16;   // K stored [tok][h], col_major
                wmma::load_matrix_sync(fbh, sKh + bo, ALD);
                wmma::load_matrix_sync(fbl, sKl + bo, ALD);
                wmma::mma_sync(cs[nf], fah, fbh, cs[nf]);
                wmma::mma_sync(cs[nf], fah, fbl, cs[nf]);
                wmma::mma_sync(cs[nf], fal, fbh, cs[nf]);
            }
        }
#pragma unroll
        for (int nf = 0; nf < 4; nf++)
            wmma::store_matrix_sync(sSP + (wid * 16) * SLD + nf * 16, cs[nf], SLD, wmma::mem_row_major);
        __syncwarp();

        // ---- online softmax (base-2 domain) ----
        float sv[32];
#pragma unroll
        for (int j = 0; j < 32; j++) sv[j] = srow[j];
        if (jt == qt) {
#pragma unroll
            for (int j = 0; j < 32; j++)
                if (ch * 32 + j > rl) sv[j] = -1e30f;
        }
        float mx = sv[0];
#pragma unroll
        for (int j = 1; j < 32; j++) mx = fmaxf(mx, sv[j]);
        mx = fmaxf(mx, __shfl_xor_sync(0xffffffffu, mx, 1));
        const float mn    = fmaxf(m, mx);
        const float alpha = fexp2(fmaxf(m - mn, -125.f));
        float sum = 0.f;
        __nv_bfloat16* ph = sPh + rl * ALD + ch * 32;
        __nv_bfloat16* pl = sPl + rl * ALD + ch * 32;
#pragma unroll
        for (int j = 0; j < 32; j += 2) {
            const float p0 = fexp2(fmaxf(sv[j]     - mn, -125.f));
            const float p1 = fexp2(fmaxf(sv[j + 1] - mn, -125.f));
            sum += p0 + p1;
            uint32_t hp, lp;
            split2(p0, p1, hp, lp);
            *(uint32_t*)(ph + j) = hp;
            *(uint32_t*)(pl + j) = lp;
        }
        sum += __shfl_xor_sync(0xffffffffu, sum, 1);
        l = l * alpha + sum;
        m = mn;
#pragma unroll
        for (int j = 0; j < 32; j++) O[j] *= alpha;
        __syncwarp();

        // ---- O += P @ V ----
        wmma::fragment<wmma::accumulator, 16, 16, 16, float> co[4];
#pragma unroll
        for (int nf = 0; nf < 4; nf++) wmma::fill_fragment(co[nf], 0.f);
#pragma unroll
        for (int ks = 0; ks < 4; ks++) {
            wmma::fragment<wmma::matrix_a, 16, 16, 16, __nv_bfloat16, wmma::row_major> fph, fpl;
            const int ao = (wid * 16) * ALD + ks * 16;
            wmma::load_matrix_sync(fph, sPh + ao, ALD);
            wmma::load_matrix_sync(fpl, sPl + ao, ALD);
#pragma unroll
            for (int nf = 0; nf < 4; nf++) {
                wmma::fragment<wmma::matrix_b, 16, 16, 16, __nv_bfloat16, wmma::row_major> fvh, fvl;
                const int bo = (ks * 16) * ALD + nf * 16;   // V stored [tok][h], row_major
                wmma::load_matrix_sync(fvh, sVh + bo, ALD);
                wmma::load_matrix_sync(fvl, sVl + bo, ALD);
                wmma::mma_sync(co[nf], fph, fvh, co[nf]);
                wmma::mma_sync(co[nf], fph, fvl, co[nf]);
                wmma::mma_sync(co[nf], fpl, fvh, co[nf]);
            }
        }
#pragma unroll
        for (int nf = 0; nf < 4; nf++)
            wmma::store_matrix_sync(sSP + (wid * 16) * SLD + nf * 16, co[nf], SLD, wmma::mem_row_major);
        __syncwarp();
#pragma unroll
        for (int j = 0; j < 32; j++) O[j] += srow[j];
    }

    // ---- normalize + write ----
    const float inv = 1.f / l;
    float* op = out + (size_t)(b * Tt + q0 + rl) * Hh + ch * 32;
#pragma unroll
    for (int j = 0; j < 32; j += 4) {
        float4 v = make_float4(O[j] * inv, O[j + 1] * inv, O[j + 2] * inv, O[j + 3] * inv);
        *(float4*)(op + j) = v;
    }
}

// ---------------------------------------------------------------------------
// Harness entry
// ---------------------------------------------------------------------------
extern "C" void kernel_launch(void* const* d_in, const int* in_sizes, int n_in,
                              void* d_out, int out_size)
{
    const float* x  = (const float*)d_in[0];
    const float* Wk = (const float*)d_in[1];
    const float* Wq = (const float*)d_in[2];
    const float* Wv = (const float*)d_in[3];
    float* out = (float*)d_out;

    cudaFuncSetAttribute(proj_tc, cudaFuncAttributeMaxDynamicSharedMemorySize, PJ_SMEM);
    cudaFuncSetAttribute(attn_tc, cudaFuncAttributeMaxDynamicSharedMemorySize, AT_SMEM);

    prep_w<<<768, 256>>>(Wk, Wq, Wv);
    proj_tc<<<BT / 128, 256, PJ_SMEM>>>(x);
    attn_tc<<<dim3(Tt / 64, Bb), 128, AT_SMEM>>>(out);
}

// round 4
// speedup vs baseline: 1.7611x; 1.2780x over previous
#include <cuda_runtime.h>
#include <cuda_bf16.h>
#include <mma.h>
#include <cstdint>

using namespace nvcuda;

// Problem constants
#define Bb 32
#define Tt 2048
#define Cc 1024
#define Hh 64
#define BT (Bb * Tt)

// 0.125 (= H^-0.5) * log2(e): scores computed directly in base-2 domain
#define QSCALE 0.180336880111227f

// Scratch (__device__ globals; no allocation allowed)
__device__ __nv_bfloat16 g_Whi[(size_t)Cc * 192];    // [k][n]  n: 0..63 K, 64..127 Q, 128..191 V
__device__ __nv_bfloat16 g_Wlo[(size_t)Cc * 192];
__device__ __nv_bfloat16 g_qhi[(size_t)BT * Hh], g_qlo[(size_t)BT * Hh];
__device__ __nv_bfloat16 g_khi[(size_t)BT * Hh], g_klo[(size_t)BT * Hh];
__device__ __nv_bfloat16 g_vhi[(size_t)BT * Hh], g_vlo[(size_t)BT * Hh];

// ---------------------------------------------------------------------------
// Helpers
// ---------------------------------------------------------------------------
__device__ __forceinline__ float fexp2(float x) {
    float z = x + 12582912.f;
    float r = x - (z - 12582912.f);
    int   e = __float_as_int(z) << 23;
    float p = 1.3333558146428443e-3f;
    p = fmaf(p, r, 9.6181291076284770e-3f);
    p = fmaf(p, r, 5.5504108664821580e-2f);
    p = fmaf(p, r, 2.4022650695910071e-1f);
    p = fmaf(p, r, 6.9314718055994531e-1f);
    p = fmaf(p, r, 1.0f);
    return __int_as_float(__float_as_int(p) + e);
}

__device__ __forceinline__ void split2(float a, float b, uint32_t& h, uint32_t& l) {
    __nv_bfloat162 hv, lv;
    hv.x = __float2bfloat16(a); hv.y = __float2bfloat16(b);
    lv.x = __float2bfloat16(a - __bfloat162float(hv.x));
    lv.y = __float2bfloat16(b - __bfloat162float(hv.y));
    h = *(uint32_t*)&hv; l = *(uint32_t*)&lv;
}

__device__ __forceinline__ uint32_t smem_u32(const void* p) {
    uint32_t a;
    asm("{ .reg .u64 t; cvta.to.shared.u64 t, %1; cvt.u32.u64 %0, t; }" : "=r"(a) : "l"(p));
    return a;
}

#define LDSM4(r, addr) \
    asm volatile("ldmatrix.sync.aligned.m8n8.x4.shared.b16 {%0,%1,%2,%3}, [%4];" \
        : "=r"((r)[0]), "=r"((r)[1]), "=r"((r)[2]), "=r"((r)[3]) : "r"(addr))
#define LDSM4T(r, addr) \
    asm volatile("ldmatrix.sync.aligned.m8n8.x4.trans.shared.b16 {%0,%1,%2,%3}, [%4];" \
        : "=r"((r)[0]), "=r"((r)[1]), "=r"((r)[2]), "=r"((r)[3]) : "r"(addr))
#define MMA16816(d, a, b0_, b1_) \
    asm volatile("mma.sync.aligned.m16n8k16.row.col.f32.bf16.bf16.f32 " \
        "{%0,%1,%2,%3}, {%4,%5,%6,%7}, {%8,%9}, {%0,%1,%2,%3};" \
        : "+f"((d)[0]), "+f"((d)[1]), "+f"((d)[2]), "+f"((d)[3]) \
        : "r"((a)[0]), "r"((a)[1]), "r"((a)[2]), "r"((a)[3]), "r"(b0_), "r"(b1_))
#define CP_ASYNC16(dst, src) \
    asm volatile("cp.async.cg.shared.global [%0], [%1], 16;" :: "r"(dst), "l"(src))
#define CP_COMMIT() asm volatile("cp.async.commit_group;" ::: "memory")
#define CP_WAIT(n)  asm volatile("cp.async.wait_group %0;" :: "n"(n) : "memory")

// ---------------------------------------------------------------------------
// Prep: split W (with Q scale folded) into bf16 hi/lo, layout [k=1024][n=192]
// ---------------------------------------------------------------------------
__global__ __launch_bounds__(256) void prep_w(
    const float* __restrict__ Wk, const float* __restrict__ Wq, const float* __restrict__ Wv)
{
    const int idx = blockIdx.x * 256 + threadIdx.x;
    const int k = idx / 192, n = idx % 192;
    float f;
    if (n < 64)       f = Wk[k * 64 + n];
    else if (n < 128) f = Wq[k * 64 + (n - 64)] * QSCALE;
    else              f = Wv[k * 64 + (n - 128)];
    __nv_bfloat16 hi = __float2bfloat16(f);
    g_Whi[idx] = hi;
    g_Wlo[idx] = __float2bfloat16(f - __bfloat162float(hi));
}

// ---------------------------------------------------------------------------
// Projection GEMM (wmma bf16, 3-term hi/lo): CTA = 128 rows x 192 cols, K=1024
// ---------------------------------------------------------------------------
#define PA_LD 80
#define PB_LD 208
#define PC_LD 104
#define PJ_A_HI 0
#define PJ_A_LO 20480
#define PJ_B_HI 40960
#define PJ_B_LO 67584
#define PJ_SMEM 94208

__global__ __launch_bounds__(256) void proj_tc(const float* __restrict__ x)
{
    extern __shared__ char smp[];
    __nv_bfloat16* sAh = (__nv_bfloat16*)(smp + PJ_A_HI);
    __nv_bfloat16* sAl = (__nv_bfloat16*)(smp + PJ_A_LO);
    __nv_bfloat16* sBh = (__nv_bfloat16*)(smp + PJ_B_HI);
    __nv_bfloat16* sBl = (__nv_bfloat16*)(smp + PJ_B_LO);
    float* sC = (float*)smp;

    const int tid = threadIdx.x;
    const int wid = tid >> 5;
    const int wm  = wid >> 1;
    const int wn  = wid & 1;
    const int row0 = blockIdx.x * 128;

    wmma::fragment<wmma::accumulator, 16, 16, 16, float> c[2][6];
#pragma unroll
    for (int mi = 0; mi < 2; mi++)
#pragma unroll
        for (int ni = 0; ni < 6; ni++) wmma::fill_fragment(c[mi][ni], 0.f);

    const int ar = tid >> 1, ah_ = tid & 1;

    for (int s = 0; s < 16; s++) {
        const int c0 = s * 64;
        __syncthreads();
        {
            const float* src = x + (size_t)(row0 + ar) * Cc + c0 + ah_ * 32;
            char* dh = (char*)sAh + ar * (PA_LD * 2) + ah_ * 64;
            char* dl = (char*)sAl + ar * (PA_LD * 2) + ah_ * 64;
#pragma unroll
            for (int i = 0; i < 8; i++) {
                float4 f = ((const float4*)src)[i];
                uint2 hv, lv;
                split2(f.x, f.y, hv.x, lv.x);
                split2(f.z, f.w, hv.y, lv.y);
                *(uint2*)(dh + i * 8) = hv;
                *(uint2*)(dl + i * 8) = lv;
            }
        }
#pragma unroll
        for (int i = 0; i < 6; i++) {
            const int idx = i * 256 + tid;
            const int r = idx / 24, cg = idx % 24;
            const size_t gsrc = (size_t)(c0 + r) * 192;
            *((uint4*)((char*)sBh + r * (PB_LD * 2)) + cg) = *((const uint4*)(g_Whi + gsrc) + cg);
            *((uint4*)((char*)sBl + r * (PB_LD * 2)) + cg) = *((const uint4*)(g_Wlo + gsrc) + cg);
        }
        __syncthreads();

#pragma unroll
        for (int ks = 0; ks < 4; ks++) {
            wmma::fragment<wmma::matrix_a, 16, 16, 16, __nv_bfloat16, wmma::row_major> fah[2], fal[2];
#pragma unroll
            for (int mi = 0; mi < 2; mi++) {
                const int ro = (wm * 32 + mi * 16) * PA_LD + ks * 16;
                wmma::load_matrix_sync(fah[mi], sAh + ro, PA_LD);
                wmma::load_matrix_sync(fal[mi], sAl + ro, PA_LD);
            }
#pragma unroll
            for (int ni = 0; ni < 6; ni++) {
                wmma::fragment<wmma::matrix_b, 16, 16, 16, __nv_bfloat16, wmma::row_major> fbh, fbl;
                const int bo = ks * 16 * PB_LD + wn * 96 + ni * 16;
                wmma::load_matrix_sync(fbh, sBh + bo, PB_LD);
                wmma::load_matrix_sync(fbl, sBl + bo, PB_LD);
#pragma unroll
                for (int mi = 0; mi < 2; mi++) {
                    wmma::mma_sync(c[mi][ni], fah[mi], fbh, c[mi][ni]);
                    wmma::mma_sync(c[mi][ni], fah[mi], fbl, c[mi][ni]);
                    wmma::mma_sync(c[mi][ni], fal[mi], fbh, c[mi][ni]);
                }
            }
        }
    }

    for (int pass = 0; pass < 2; pass++) {
        __syncthreads();
        if (wn == pass) {
#pragma unroll
            for (int mi = 0; mi < 2; mi++)
#pragma unroll
                for (int ni = 0; ni < 6; ni++)
                    wmma::store_matrix_sync(sC + (wm * 32 + mi * 16) * PC_LD + ni * 16,
                                            c[mi][ni], PC_LD, wmma::mem_row_major);
        }
        __syncthreads();
        const int r = tid >> 1, hf = tid & 1;
        const size_t gr = (size_t)(row0 + r) * Hh;
        const float* src = sC + r * PC_LD + hf * 48;
#pragma unroll
        for (int j = 0; j < 48; j += 2) {
            const int col = pass * 96 + hf * 48 + j;
            uint32_t hp, lp;
            split2(src[j], src[j + 1], hp, lp);
            __nv_bfloat16 *dh, *dl; int cc;
            if (col < 64)       { dh = g_khi; dl = g_klo; cc = col; }
            else if (col < 128) { dh = g_qhi; dl = g_qlo; cc = col - 64; }
            else                { dh = g_vhi; dl = g_vlo; cc = col - 128; }
            *(uint32_t*)(dh + gr + cc) = hp;
            *(uint32_t*)(dl + gr + cc) = lp;
        }
    }
}

// ---------------------------------------------------------------------------
// Flash attention, FA2-style mma.sync: 8 warps, 128 q-rows/CTA, register
// softmax, cp.async double-buffered K/V. smem stride 144B (conflict-free ldsm).
// ---------------------------------------------------------------------------
#define RSTRIDE 144                        // bytes per 64-col bf16 row
#define QH_OFF  0
#define QL_OFF  18432
#define KV_OFF  36864                      // per buf: KH,KL,VH,VL each 9216
#define KVBUF   36864
#define AT_SMEM 110592

__global__ __launch_bounds__(256, 2) void attn_tc(float* __restrict__ out)
{
    extern __shared__ char sma[];
    const uint32_t sb  = smem_u32(sma);
    const uint32_t sQh = sb + QH_OFF;
    const uint32_t sQl = sb + QL_OFF;

    const int tid  = threadIdx.x;
    const int w    = tid >> 5;
    const int lane = tid & 31;
    const int b    = blockIdx.y;
    const int it   = (Tt / 128 - 1) - blockIdx.x;    // reverse schedule
    const int q0   = it * 128;
    const int jmax = 2 * it + 1;

    const int gid = lane >> 2, tig = lane & 3;
    const int lr  = lane & 7,  grp = lane >> 3;

    // per-lane ldmatrix byte offsets within a tile region
    const uint32_t aQ = (uint32_t)((16 * w + lr + (grp & 1) * 8) * RSTRIDE + (grp >> 1) * 16);
    const uint32_t aK = (uint32_t)((lr + (grp >> 1) * 8) * RSTRIDE + (grp & 1) * 16);
    const uint32_t aV = (uint32_t)((lr + (grp & 1) * 8) * RSTRIDE + (grp >> 1) * 16);

    // ---- prologue: cp.async Q (hi/lo) + KV tile 0 ----
#pragma unroll
    for (int i = 0; i < 4; i++) {
        const int idx = i * 256 + tid;        // 0..1023
        const int r = idx >> 3, cg = idx & 7;
        const size_t gof = (size_t)(b * Tt + q0 + r) * Hh + cg * 8;
        CP_ASYNC16(sQh + r * RSTRIDE + cg * 16, (const char*)(g_qhi + gof));
        CP_ASYNC16(sQl + r * RSTRIDE + cg * 16, (const char*)(g_qlo + gof));
    }
#pragma unroll
    for (int i = 0; i < 2; i++) {
        const int idx = i * 256 + tid;        // 0..511
        const int r = idx >> 3, cg = idx & 7;
        const size_t gof = (size_t)(b * Tt + r) * Hh + cg * 8;
        const uint32_t d0 = sb + KV_OFF + r * RSTRIDE + cg * 16;
        CP_ASYNC16(d0,         (const char*)(g_khi + gof));
        CP_ASYNC16(d0 + 9216,  (const char*)(g_klo + gof));
        CP_ASYNC16(d0 + 18432, (const char*)(g_vhi + gof));
        CP_ASYNC16(d0 + 27648, (const char*)(g_vlo + gof));
    }
    CP_COMMIT();

    float o[8][4];
#pragma unroll
    for (int nt = 0; nt < 8; nt++)
#pragma unroll
        for (int e = 0; e < 4; e++) o[nt][e] = 0.f;
    float m0 = -1e30f, m1 = -1e30f, l0 = 0.f, l1 = 0.f;

    const int r1g = q0 + 16 * w + gid;        // global row (lower half)
    const int r2g = r1g + 8;

    for (int jt = 0; jt <= jmax; jt++) {
        // prefetch next tile into the other buffer
        if (jt < jmax) {
            const int jn = (jt + 1) * 64;
            const uint32_t bufn = sb + KV_OFF + ((jt + 1) & 1) * KVBUF;
#pragma unroll
            for (int i = 0; i < 2; i++) {
                const int idx = i * 256 + tid;
                const int r = idx >> 3, cg = idx & 7;
                const size_t gof = (size_t)(b * Tt + jn + r) * Hh + cg * 8;
                const uint32_t d0 = bufn + r * RSTRIDE + cg * 16;
                CP_ASYNC16(d0,         (const char*)(g_khi + gof));
                CP_ASYNC16(d0 + 9216,  (const char*)(g_klo + gof));
                CP_ASYNC16(d0 + 18432, (const char*)(g_vhi + gof));
                CP_ASYNC16(d0 + 27648, (const char*)(g_vlo + gof));
            }
            CP_COMMIT();
            CP_WAIT(1);
        } else {
            CP_WAIT(0);
        }
        __syncthreads();

        const int j0 = jt * 64;
        const bool skip = (j0 > q0 + 16 * w + 15);
        if (!skip) {
            const uint32_t buf = sb + KV_OFF + (jt & 1) * KVBUF;

            // ---- S = Q @ K^T ----
            float s[8][4];
#pragma unroll
            for (int nt = 0; nt < 8; nt++)
#pragma unroll
                for (int e = 0; e < 4; e++) s[nt][e] = 0.f;

#pragma unroll
            for (int ks = 0; ks < 4; ks++) {
                uint32_t qh[4], ql[4];
                LDSM4(qh, sQh + aQ + ks * 32);
                LDSM4(ql, sQl + aQ + ks * 32);
#pragma unroll
                for (int ntp = 0; ntp < 4; ntp++) {
                    uint32_t bh[4], bl[4];
                    const uint32_t ka = buf + aK + ntp * (16 * RSTRIDE) + ks * 32;
                    LDSM4(bh, ka);
                    LDSM4(bl, ka + 9216);
                    MMA16816(s[2 * ntp],     qh, bh[0], bh[1]);
                    MMA16816(s[2 * ntp],     qh, bl[0], bl[1]);
                    MMA16816(s[2 * ntp],     ql, bh[0], bh[1]);
                    MMA16816(s[2 * ntp + 1], qh, bh[2], bh[3]);
                    MMA16816(s[2 * ntp + 1], qh, bl[2], bl[3]);
                    MMA16816(s[2 * ntp + 1], ql, bh[2], bh[3]);
                }
            }

            // ---- causal mask ----
            if (j0 + 63 > q0 + 16 * w) {
#pragma unroll
                for (int nt = 0; nt < 8; nt++) {
                    const int cbase = j0 + 8 * nt + 2 * tig;
                    if (cbase     > r1g) s[nt][0] = -1e30f;
                    if (cbase + 1 > r1g) s[nt][1] = -1e30f;
                    if (cbase     > r2g) s[nt][2] = -1e30f;
                    if (cbase + 1 > r2g) s[nt][3] = -1e30f;
                }
            }

            // ---- register online softmax (rows in quads) ----
            float mx0 = s[0][0], mx1 = s[0][2];
#pragma unroll
            for (int nt = 0; nt < 8; nt++) {
                mx0 = fmaxf(mx0, fmaxf(s[nt][0], s[nt][1]));
                mx1 = fmaxf(mx1, fmaxf(s[nt][2], s[nt][3]));
            }
            mx0 = fmaxf(mx0, __shfl_xor_sync(0xffffffffu, mx0, 1));
            mx0 = fmaxf(mx0, __shfl_xor_sync(0xffffffffu, mx0, 2));
            mx1 = fmaxf(mx1, __shfl_xor_sync(0xffffffffu, mx1, 1));
            mx1 = fmaxf(mx1, __shfl_xor_sync(0xffffffffu, mx1, 2));
            const float mn0 = fmaxf(m0, mx0), mn1 = fmaxf(m1, mx1);
            const float a0 = fexp2(fmaxf(m0 - mn0, -125.f));
            const float a1 = fexp2(fmaxf(m1 - mn1, -125.f));
            float sum0 = 0.f, sum1 = 0.f;
#pragma unroll
            for (int nt = 0; nt < 8; nt++) {
                s[nt][0] = fexp2(fmaxf(s[nt][0] - mn0, -125.f));
                s[nt][1] = fexp2(fmaxf(s[nt][1] - mn0, -125.f));
                s[nt][2] = fexp2(fmaxf(s[nt][2] - mn1, -125.f));
                s[nt][3] = fexp2(fmaxf(s[nt][3] - mn1, -125.f));
                sum0 += s[nt][0] + s[nt][1];
                sum1 += s[nt][2] + s[nt][3];
            }
            sum0 += __shfl_xor_sync(0xffffffffu, sum0, 1);
            sum0 += __shfl_xor_sync(0xffffffffu, sum0, 2);
            sum1 += __shfl_xor_sync(0xffffffffu, sum1, 1);
            sum1 += __shfl_xor_sync(0xffffffffu, sum1, 2);
            l0 = l0 * a0 + sum0;
            l1 = l1 * a1 + sum1;
            m0 = mn0; m1 = mn1;
#pragma unroll
            for (int nt = 0; nt < 8; nt++) {
                o[nt][0] *= a0; o[nt][1] *= a0;
                o[nt][2] *= a1; o[nt][3] *= a1;
            }

            // ---- O += P @ V  (P packed from s in registers) ----
#pragma unroll
            for (int kt = 0; kt < 4; kt++) {
                uint32_t ah[4], al[4];
                split2(s[2 * kt][0],     s[2 * kt][1],     ah[0], al[0]);
                split2(s[2 * kt][2],     s[2 * kt][3],     ah[1], al[1]);
                split2(s[2 * kt + 1][0], s[2 * kt + 1][1], ah[2], al[2]);
                split2(s[2 * kt + 1][2], s[2 * kt + 1][3], ah[3], al[3]);
#pragma unroll
                for (int nhp = 0; nhp < 4; nhp++) {
                    uint32_t bh[4], bl[4];
                    const uint32_t va = buf + 18432 + aV + kt * (16 * RSTRIDE) + nhp * 32;
                    LDSM4T(bh, va);
                    LDSM4T(bl, va + 9216);
                    MMA16816(o[2 * nhp],     ah, bh[0], bh[1]);
                    MMA16816(o[2 * nhp],     ah, bl[0], bl[1]);
                    MMA16816(o[2 * nhp],     al, bh[0], bh[1]);
                    MMA16816(o[2 * nhp + 1], ah, bh[2], bh[3]);
                    MMA16816(o[2 * nhp + 1], ah, bl[2], bl[3]);
                    MMA16816(o[2 * nhp + 1], al, bh[2], bh[3]);
                }
            }
        }
        __syncthreads();   // all warps done reading this buffer before reuse
    }

    // ---- normalize + write (float2 per fragment slot) ----
    const float inv0 = 1.f / l0, inv1 = 1.f / l1;
    float* o1 = out + ((size_t)b * Tt + r1g) * Hh + 2 * tig;
    float* o2 = out + ((size_t)b * Tt + r2g) * Hh + 2 * tig;
#pragma unroll
    for (int nt = 0; nt < 8; nt++) {
        *(float2*)(o1 + 8 * nt) = make_float2(o[nt][0] * inv0, o[nt][1] * inv0);
        *(float2*)(o2 + 8 * nt) = make_float2(o[nt][2] * inv1, o[nt][3] * inv1);
    }
}

// ---------------------------------------------------------------------------
// Harness entry
// ---------------------------------------------------------------------------
extern "C" void kernel_launch(void* const* d_in, const int* in_sizes, int n_in,
                              void* d_out, int out_size)
{
    const float* x  = (const float*)d_in[0];
    const float* Wk = (const float*)d_in[1];
    const float* Wq = (const float*)d_in[2];
    const float* Wv = (const float*)d_in[3];
    float* out = (float*)d_out;

    cudaFuncSetAttribute(proj_tc, cudaFuncAttributeMaxDynamicSharedMemorySize, PJ_SMEM);
    cudaFuncSetAttribute(attn_tc, cudaFuncAttributeMaxDynamicSharedMemorySize, AT_SMEM);

    prep_w<<<768, 256>>>(Wk, Wq, Wv);
    proj_tc<<<BT / 128, 256, PJ_SMEM>>>(x);
    attn_tc<<<dim3(Tt / 128, Bb), 256, AT_SMEM>>>(out);
}

// round 5
// speedup vs baseline: 2.4906x; 1.4143x over previous
#include <cuda_runtime.h>
#include <cuda_bf16.h>
#include <cstdint>

// Problem constants
#define Bb 32
#define Tt 2048
#define Cc 1024
#define Hh 64
#define BT (Bb * Tt)

// 0.125 (= H^-0.5) * log2(e): scores computed directly in base-2 domain
#define QSCALE 0.180336880111227f

// Scratch (__device__ globals; no allocation allowed)
__device__ __nv_bfloat16 g_Whi[(size_t)Cc * 192];    // [k][n]  n: 0..63 K, 64..127 Q, 128..191 V
__device__ __nv_bfloat16 g_Wlo[(size_t)Cc * 192];
__device__ __nv_bfloat16 g_qhi[(size_t)BT * Hh], g_qlo[(size_t)BT * Hh];
__device__ __nv_bfloat16 g_khi[(size_t)BT * Hh], g_klo[(size_t)BT * Hh];
__device__ __nv_bfloat16 g_vhi[(size_t)BT * Hh], g_vlo[(size_t)BT * Hh];

// ---------------------------------------------------------------------------
// Helpers
// ---------------------------------------------------------------------------
__device__ __forceinline__ float fexp2(float x) {
    float z = x + 12582912.f;
    float r = x - (z - 12582912.f);
    int   e = __float_as_int(z) << 23;
    float p = 1.3333558146428443e-3f;
    p = fmaf(p, r, 9.6181291076284770e-3f);
    p = fmaf(p, r, 5.5504108664821580e-2f);
    p = fmaf(p, r, 2.4022650695910071e-1f);
    p = fmaf(p, r, 6.9314718055994531e-1f);
    p = fmaf(p, r, 1.0f);
    return __int_as_float(__float_as_int(p) + e);
}

__device__ __forceinline__ void split2(float a, float b, uint32_t& h, uint32_t& l) {
    __nv_bfloat162 hv, lv;
    hv.x = __float2bfloat16(a); hv.y = __float2bfloat16(b);
    lv.x = __float2bfloat16(a - __bfloat162float(hv.x));
    lv.y = __float2bfloat16(b - __bfloat162float(hv.y));
    h = *(uint32_t*)&hv; l = *(uint32_t*)&lv;
}

__device__ __forceinline__ uint32_t smem_u32(const void* p) {
    uint32_t a;
    asm("{ .reg .u64 t; cvta.to.shared.u64 t, %1; cvt.u32.u64 %0, t; }" : "=r"(a) : "l"(p));
    return a;
}

#define LDSM4(r, addr) \
    asm volatile("ldmatrix.sync.aligned.m8n8.x4.shared.b16 {%0,%1,%2,%3}, [%4];" \
        : "=r"((r)[0]), "=r"((r)[1]), "=r"((r)[2]), "=r"((r)[3]) : "r"(addr))
#define LDSM4T(r, addr) \
    asm volatile("ldmatrix.sync.aligned.m8n8.x4.trans.shared.b16 {%0,%1,%2,%3}, [%4];" \
        : "=r"((r)[0]), "=r"((r)[1]), "=r"((r)[2]), "=r"((r)[3]) : "r"(addr))
#define MMA16816(d, a, b0_, b1_) \
    asm volatile("mma.sync.aligned.m16n8k16.row.col.f32.bf16.bf16.f32 " \
        "{%0,%1,%2,%3}, {%4,%5,%6,%7}, {%8,%9}, {%0,%1,%2,%3};" \
        : "+f"((d)[0]), "+f"((d)[1]), "+f"((d)[2]), "+f"((d)[3]) \
        : "r"((a)[0]), "r"((a)[1]), "r"((a)[2]), "r"((a)[3]), "r"(b0_), "r"(b1_))
#define CP_ASYNC16(dst, src) \
    asm volatile("cp.async.cg.shared.global [%0], [%1], 16;" :: "r"(dst), "l"(src))
#define CP_COMMIT() asm volatile("cp.async.commit_group;" ::: "memory")
#define CP_WAIT(n)  asm volatile("cp.async.wait_group %0;" :: "n"(n) : "memory")

// ---------------------------------------------------------------------------
// Prep: split W (with Q scale folded) into bf16 hi/lo, layout [k=1024][n=192]
// ---------------------------------------------------------------------------
__global__ __launch_bounds__(256) void prep_w(
    const float* __restrict__ Wk, const float* __restrict__ Wq, const float* __restrict__ Wv)
{
    const int idx = blockIdx.x * 256 + threadIdx.x;
    const int k = idx / 192, n = idx % 192;
    float f;
    if (n < 64)       f = Wk[k * 64 + n];
    else if (n < 128) f = Wq[k * 64 + (n - 64)] * QSCALE;
    else              f = Wv[k * 64 + (n - 128)];
    __nv_bfloat16 hi = __float2bfloat16(f);
    g_Whi[idx] = hi;
    g_Wlo[idx] = __float2bfloat16(f - __bfloat162float(hi));
}

// ---------------------------------------------------------------------------
// Projection GEMM, pipelined mma.sync: CTA = 128 rows x 192 cols, K chunks of
// 64. cp.async double-buffered W (hi/lo), single-buffered fp32 x staging with
// in-smem bf16 hi/lo conversion (XOR-swizzled, 128B stride). Direct register
// epilogue to q/k/v bf16 hi/lo. 8 warps: wm 0..3 (32 rows), wn 0..1 (96 cols).
// ---------------------------------------------------------------------------
#define SGX_OFF  0                 // fp32 stage: 128x64x4 = 32768
#define SAH_OFF  32768             // A hi, swizzled, 128 rows x 128B = 16384
#define SAL_OFF  49152
#define SB_OFF   65536             // two buffers x (hi 25600 + lo 25600)
#define SB_BUF   51200
#define BSTRIDE  400               // 192 cols x 2B + 16B pad (mod 128 = 16)
#define PJ_SMEM  167936

__global__ __launch_bounds__(256) void proj_tc(const float* __restrict__ x)
{
    extern __shared__ char smp[];
    const uint32_t sb = smem_u32(smp);
    const int tid  = threadIdx.x;
    const int wid  = tid >> 5;
    const int lane = tid & 31;
    const int wm   = wid >> 1;
    const int wn   = wid & 1;
    const int row0 = blockIdx.x * 128;

    const int gid = lane >> 2, tig = lane & 3;
    const int lr  = lane & 7,  grp = lane >> 3;

    float acc[2][12][4];
#pragma unroll
    for (int mi = 0; mi < 2; mi++)
#pragma unroll
        for (int j = 0; j < 12; j++)
#pragma unroll
            for (int e = 0; e < 4; e++) acc[mi][j][e] = 0.f;

    // per-lane ldsm row bases
    int rowA[2];
#pragma unroll
    for (int mi = 0; mi < 2; mi++) rowA[mi] = wm * 32 + mi * 16 + lr + (grp & 1) * 8;
    const int ac16g = grp >> 1;                          // A col-16 group half
    const uint32_t bofs = (uint32_t)((lr + (grp & 1) * 8) * BSTRIDE + wn * 192 + (grp >> 1) * 16);

    // ---- prologue: cp.async chunk 0 (x stage + W buf0) ----
#pragma unroll
    for (int i = 0; i < 8; i++) {
        const int u = i * 256 + tid;                     // < 2048
        const int r = u >> 4, c4 = u & 15;
        CP_ASYNC16(sb + SGX_OFF + u * 16, (const char*)(x + (size_t)(row0 + r) * Cc + c4 * 4));
    }
#pragma unroll
    for (int i = 0; i < 6; i++) {
        const int u = i * 256 + tid;                     // < 1536
        const int r = u / 24, cg = u % 24;
        const uint32_t d = sb + SB_OFF + r * BSTRIDE + cg * 16;
        const size_t   s = (size_t)r * 192 + cg * 8;
        CP_ASYNC16(d,         (const char*)(g_Whi + s));
        CP_ASYNC16(d + 25600, (const char*)(g_Wlo + s));
    }
    CP_COMMIT();

    for (int c = 0; c < 16; c++) {
        const int p = c & 1;
        CP_WAIT(0);
        __syncthreads();                                  // mma(c-1) done with SA & SB(p^1)

        // ---- convert stage fp32 -> SA hi/lo (swizzled) ----
#pragma unroll
        for (int i = 0; i < 4; i++) {
            const int u = i * 256 + tid;                  // < 1024
            const int r = u >> 3, c16 = u & 7;
            const float4* st = (const float4*)(smp + SGX_OFF + r * 256 + c16 * 32);
            const float4 f0 = st[0], f1 = st[1];
            uint4 hv, lv;
            split2(f0.x, f0.y, hv.x, lv.x);
            split2(f0.z, f0.w, hv.y, lv.y);
            split2(f1.x, f1.y, hv.z, lv.z);
            split2(f1.z, f1.w, hv.w, lv.w);
            const uint32_t off = (uint32_t)(r * 128 + ((c16 ^ (r & 7)) << 4));
            *(uint4*)(smp + SAH_OFF + off) = hv;
            *(uint4*)(smp + SAL_OFF + off) = lv;
        }
        __syncthreads();                                  // SA visible; stage free

        // ---- issue next chunk's loads (overlap with mma below) ----
        if (c < 15) {
            const int c0n = (c + 1) * 64;
#pragma unroll
            for (int i = 0; i < 8; i++) {
                const int u = i * 256 + tid;
                const int r = u >> 4, c4 = u & 15;
                CP_ASYNC16(sb + SGX_OFF + u * 16,
                           (const char*)(x + (size_t)(row0 + r) * Cc + c0n + c4 * 4));
            }
            const uint32_t bufn = sb + SB_OFF + (p ^ 1) * SB_BUF;
#pragma unroll
            for (int i = 0; i < 6; i++) {
                const int u = i * 256 + tid;
                const int r = u / 24, cg = u % 24;
                const uint32_t d = bufn + r * BSTRIDE + cg * 16;
                const size_t   s = (size_t)(c0n + r) * 192 + cg * 8;
                CP_ASYNC16(d,         (const char*)(g_Whi + s));
                CP_ASYNC16(d + 25600, (const char*)(g_Wlo + s));
            }
            CP_COMMIT();
        }

        // ---- MMA on chunk c ----
        const uint32_t bbuf = sb + SB_OFF + p * SB_BUF;
#pragma unroll
        for (int ks = 0; ks < 4; ks++) {
            uint32_t ah[2][4], al[2][4];
#pragma unroll
            for (int mi = 0; mi < 2; mi++) {
                const int c16 = 2 * ks + ac16g;
                const uint32_t aoff = (uint32_t)(rowA[mi] * 128 + ((c16 ^ lr) << 4));
                LDSM4(ah[mi], sb + SAH_OFF + aoff);
                LDSM4(al[mi], sb + SAL_OFF + aoff);
            }
#pragma unroll
            for (int nt = 0; nt < 6; nt++) {
                uint32_t bh[4], bl[4];
                const uint32_t ba = bbuf + bofs + (uint32_t)(ks * 16 * BSTRIDE + nt * 32);
                LDSM4T(bh, ba);
                LDSM4T(bl, ba + 25600);
#pragma unroll
                for (int mi = 0; mi < 2; mi++) {
                    MMA16816(acc[mi][2 * nt],     ah[mi], bh[0], bh[1]);
                    MMA16816(acc[mi][2 * nt],     ah[mi], bl[0], bl[1]);
                    MMA16816(acc[mi][2 * nt],     al[mi], bh[0], bh[1]);
                    MMA16816(acc[mi][2 * nt + 1], ah[mi], bh[2], bh[3]);
                    MMA16816(acc[mi][2 * nt + 1], ah[mi], bl[2], bl[3]);
                    MMA16816(acc[mi][2 * nt + 1], al[mi], bh[2], bh[3]);
                }
            }
        }
    }

    // ---- epilogue: direct register -> global bf16 hi/lo ----
#pragma unroll
    for (int mi = 0; mi < 2; mi++) {
        const int r1 = row0 + wm * 32 + mi * 16 + gid;
        const int r2 = r1 + 8;
#pragma unroll
        for (int j = 0; j < 12; j++) {
            const int col = wn * 96 + j * 8 + tig * 2;
            __nv_bfloat16 *dh, *dl; int cc;
            if (col < 64)       { dh = g_khi; dl = g_klo; cc = col; }
            else if (col < 128) { dh = g_qhi; dl = g_qlo; cc = col - 64; }
            else                { dh = g_vhi; dl = g_vlo; cc = col - 128; }
            uint32_t h1, l1, h2, l2;
            split2(acc[mi][j][0], acc[mi][j][1], h1, l1);
            split2(acc[mi][j][2], acc[mi][j][3], h2, l2);
            *(uint32_t*)(dh + (size_t)r1 * Hh + cc) = h1;
            *(uint32_t*)(dl + (size_t)r1 * Hh + cc) = l1;
            *(uint32_t*)(dh + (size_t)r2 * Hh + cc) = h2;
            *(uint32_t*)(dl + (size_t)r2 * Hh + cc) = l2;
        }
    }
}

// ---------------------------------------------------------------------------
// Flash attention, FA2-style mma.sync: 8 warps, 128 q-rows/CTA, register
// softmax, cp.async double-buffered K/V. smem stride 144B (conflict-free ldsm).
// ---------------------------------------------------------------------------
#define RSTRIDE 144
#define QH_OFF  0
#define QL_OFF  18432
#define KV_OFF  36864
#define KVBUF   36864
#define AT_SMEM 110592

__global__ __launch_bounds__(256, 2) void attn_tc(float* __restrict__ out)
{
    extern __shared__ char sma[];
    const uint32_t sb  = smem_u32(sma);
    const uint32_t sQh = sb + QH_OFF;
    const uint32_t sQl = sb + QL_OFF;

    const int tid  = threadIdx.x;
    const int w    = tid >> 5;
    const int lane = tid & 31;
    const int b    = blockIdx.y;
    const int it   = (Tt / 128 - 1) - blockIdx.x;
    const int q0   = it * 128;
    const int jmax = 2 * it + 1;

    const int gid = lane >> 2, tig = lane & 3;
    const int lr  = lane & 7,  grp = lane >> 3;

    const uint32_t aQ = (uint32_t)((16 * w + lr + (grp & 1) * 8) * RSTRIDE + (grp >> 1) * 16);
    const uint32_t aK = (uint32_t)((lr + (grp >> 1) * 8) * RSTRIDE + (grp & 1) * 16);
    const uint32_t aV = (uint32_t)((lr + (grp & 1) * 8) * RSTRIDE + (grp >> 1) * 16);

#pragma unroll
    for (int i = 0; i < 4; i++) {
        const int idx = i * 256 + tid;
        const int r = idx >> 3, cg = idx & 7;
        const size_t gof = (size_t)(b * Tt + q0 + r) * Hh + cg * 8;
        CP_ASYNC16(sQh + r * RSTRIDE + cg * 16, (const char*)(g_qhi + gof));
        CP_ASYNC16(sQl + r * RSTRIDE + cg * 16, (const char*)(g_qlo + gof));
    }
#pragma unroll
    for (int i = 0; i < 2; i++) {
        const int idx = i * 256 + tid;
        const int r = idx >> 3, cg = idx & 7;
        const size_t gof = (size_t)(b * Tt + r) * Hh + cg * 8;
        const uint32_t d0 = sb + KV_OFF + r * RSTRIDE + cg * 16;
        CP_ASYNC16(d0,         (const char*)(g_khi + gof));
        CP_ASYNC16(d0 + 9216,  (const char*)(g_klo + gof));
        CP_ASYNC16(d0 + 18432, (const char*)(g_vhi + gof));
        CP_ASYNC16(d0 + 27648, (const char*)(g_vlo + gof));
    }
    CP_COMMIT();

    float o[8][4];
#pragma unroll
    for (int nt = 0; nt < 8; nt++)
#pragma unroll
        for (int e = 0; e < 4; e++) o[nt][e] = 0.f;
    float m0 = -1e30f, m1 = -1e30f, l0 = 0.f, l1 = 0.f;

    const int r1g = q0 + 16 * w + gid;
    const int r2g = r1g + 8;

    for (int jt = 0; jt <= jmax; jt++) {
        if (jt < jmax) {
            const int jn = (jt + 1) * 64;
            const uint32_t bufn = sb + KV_OFF + ((jt + 1) & 1) * KVBUF;
#pragma unroll
            for (int i = 0; i < 2; i++) {
                const int idx = i * 256 + tid;
                const int r = idx >> 3, cg = idx & 7;
                const size_t gof = (size_t)(b * Tt + jn + r) * Hh + cg * 8;
                const uint32_t d0 = bufn + r * RSTRIDE + cg * 16;
                CP_ASYNC16(d0,         (const char*)(g_khi + gof));
                CP_ASYNC16(d0 + 9216,  (const char*)(g_klo + gof));
                CP_ASYNC16(d0 + 18432, (const char*)(g_vhi + gof));
                CP_ASYNC16(d0 + 27648, (const char*)(g_vlo + gof));
            }
            CP_COMMIT();
            CP_WAIT(1);
        } else {
            CP_WAIT(0);
        }
        __syncthreads();

        const int j0 = jt * 64;
        const bool skip = (j0 > q0 + 16 * w + 15);
        if (!skip) {
            const uint32_t buf = sb + KV_OFF + (jt & 1) * KVBUF;

            float s[8][4];
#pragma unroll
            for (int nt = 0; nt < 8; nt++)
#pragma unroll
                for (int e = 0; e < 4; e++) s[nt][e] = 0.f;

#pragma unroll
            for (int ks = 0; ks < 4; ks++) {
                uint32_t qh[4], ql[4];
                LDSM4(qh, sQh + aQ + ks * 32);
                LDSM4(ql, sQl + aQ + ks * 32);
#pragma unroll
                for (int ntp = 0; ntp < 4; ntp++) {
                    uint32_t bh[4], bl[4];
                    const uint32_t ka = buf + aK + ntp * (16 * RSTRIDE) + ks * 32;
                    LDSM4(bh, ka);
                    LDSM4(bl, ka + 9216);
                    MMA16816(s[2 * ntp],     qh, bh[0], bh[1]);
                    MMA16816(s[2 * ntp],     qh, bl[0], bl[1]);
                    MMA16816(s[2 * ntp],     ql, bh[0], bh[1]);
                    MMA16816(s[2 * ntp + 1], qh, bh[2], bh[3]);
                    MMA16816(s[2 * ntp + 1], qh, bl[2], bl[3]);
                    MMA16816(s[2 * ntp + 1], ql, bh[2], bh[3]);
                }
            }

            if (j0 + 63 > q0 + 16 * w) {
#pragma unroll
                for (int nt = 0; nt < 8; nt++) {
                    const int cbase = j0 + 8 * nt + 2 * tig;
                    if (cbase     > r1g) s[nt][0] = -1e30f;
                    if (cbase + 1 > r1g) s[nt][1] = -1e30f;
                    if (cbase     > r2g) s[nt][2] = -1e30f;
                    if (cbase + 1 > r2g) s[nt][3] = -1e30f;
                }
            }

            float mx0 = s[0][0], mx1 = s[0][2];
#pragma unroll
            for (int nt = 0; nt < 8; nt++) {
                mx0 = fmaxf(mx0, fmaxf(s[nt][0], s[nt][1]));
                mx1 = fmaxf(mx1, fmaxf(s[nt][2], s[nt][3]));
            }
            mx0 = fmaxf(mx0, __shfl_xor_sync(0xffffffffu, mx0, 1));
            mx0 = fmaxf(mx0, __shfl_xor_sync(0xffffffffu, mx0, 2));
            mx1 = fmaxf(mx1, __shfl_xor_sync(0xffffffffu, mx1, 1));
            mx1 = fmaxf(mx1, __shfl_xor_sync(0xffffffffu, mx1, 2));
            const float mn0 = fmaxf(m0, mx0), mn1 = fmaxf(m1, mx1);
            const float a0 = fexp2(fmaxf(m0 - mn0, -125.f));
            const float a1 = fexp2(fmaxf(m1 - mn1, -125.f));
            float sum0 = 0.f, sum1 = 0.f;
#pragma unroll
            for (int nt = 0; nt < 8; nt++) {
                s[nt][0] = fexp2(fmaxf(s[nt][0] - mn0, -125.f));
                s[nt][1] = fexp2(fmaxf(s[nt][1] - mn0, -125.f));
                s[nt][2] = fexp2(fmaxf(s[nt][2] - mn1, -125.f));
                s[nt][3] = fexp2(fmaxf(s[nt][3] - mn1, -125.f));
                sum0 += s[nt][0] + s[nt][1];
                sum1 += s[nt][2] + s[nt][3];
            }
            sum0 += __shfl_xor_sync(0xffffffffu, sum0, 1);
            sum0 += __shfl_xor_sync(0xffffffffu, sum0, 2);
            sum1 += __shfl_xor_sync(0xffffffffu, sum1, 1);
            sum1 += __shfl_xor_sync(0xffffffffu, sum1, 2);
            l0 = l0 * a0 + sum0;
            l1 = l1 * a1 + sum1;
            m0 = mn0; m1 = mn1;
#pragma unroll
            for (int nt = 0; nt < 8; nt++) {
                o[nt][0] *= a0; o[nt][1] *= a0;
                o[nt][2] *= a1; o[nt][3] *= a1;
            }

#pragma unroll
            for (int kt = 0; kt < 4; kt++) {
                uint32_t ah[4], al[4];
                split2(s[2 * kt][0],     s[2 * kt][1],     ah[0], al[0]);
                split2(s[2 * kt][2],     s[2 * kt][3],     ah[1], al[1]);
                split2(s[2 * kt + 1][0], s[2 * kt + 1][1], ah[2], al[2]);
                split2(s[2 * kt + 1][2], s[2 * kt + 1][3], ah[3], al[3]);
#pragma unroll
                for (int nhp = 0; nhp < 4; nhp++) {
                    uint32_t bh[4], bl[4];
                    const uint32_t va = buf + 18432 + aV + kt * (16 * RSTRIDE) + nhp * 32;
                    LDSM4T(bh, va);
                    LDSM4T(bl, va + 9216);
                    MMA16816(o[2 * nhp],     ah, bh[0], bh[1]);
                    MMA16816(o[2 * nhp],     ah, bl[0], bl[1]);
                    MMA16816(o[2 * nhp],     al, bh[0], bh[1]);
                    MMA16816(o[2 * nhp + 1], ah, bh[2], bh[3]);
                    MMA16816(o[2 * nhp + 1], ah, bl[2], bl[3]);
                    MMA16816(o[2 * nhp + 1], al, bh[2], bh[3]);
                }
            }
        }
        __syncthreads();
    }

    const float inv0 = 1.f / l0, inv1 = 1.f / l1;
    float* o1 = out + ((size_t)b * Tt + r1g) * Hh + 2 * tig;
    float* o2 = out + ((size_t)b * Tt + r2g) * Hh + 2 * tig;
#pragma unroll
    for (int nt = 0; nt < 8; nt++) {
        *(float2*)(o1 + 8 * nt) = make_float2(o[nt][0] * inv0, o[nt][1] * inv0);
        *(float2*)(o2 + 8 * nt) = make_float2(o[nt][2] * inv1, o[nt][3] * inv1);
    }
}

// ---------------------------------------------------------------------------
// Harness entry
// ---------------------------------------------------------------------------
extern "C" void kernel_launch(void* const* d_in, const int* in_sizes, int n_in,
                              void* d_out, int out_size)
{
    const float* x  = (const float*)d_in[0];
    const float* Wk = (const float*)d_in[1];
    const float* Wq = (const float*)d_in[2];
    const float* Wv = (const float*)d_in[3];
    float* out = (float*)d_out;

    cudaFuncSetAttribute(proj_tc, cudaFuncAttributeMaxDynamicSharedMemorySize, PJ_SMEM);
    cudaFuncSetAttribute(attn_tc, cudaFuncAttributeMaxDynamicSharedMemorySize, AT_SMEM);

    prep_w<<<768, 256>>>(Wk, Wq, Wv);
    proj_tc<<<BT / 128, 256, PJ_SMEM>>>(x);
    attn_tc<<<dim3(Tt / 128, Bb), 256, AT_SMEM>>>(out);
}

// round 6
// speedup vs baseline: 2.7772x; 1.1151x over previous
#include <cuda_runtime.h>
#include <cuda_bf16.h>
#include <cstdint>

// Problem constants
#define Bb 32
#define Tt 2048
#define Cc 1024
#define Hh 64
#define BT (Bb * Tt)

// 0.125 (= H^-0.5) * log2(e): scores computed directly in base-2 domain
#define QSCALE 0.180336880111227f

// Scratch (__device__ globals; no allocation allowed)
__device__ __nv_bfloat16 g_Whi[(size_t)Cc * 192];    // [k][n]  n: 0..63 K, 64..127 Q, 128..191 V
__device__ __nv_bfloat16 g_Wlo[(size_t)Cc * 192];
__device__ __nv_bfloat16 g_qhi[(size_t)BT * Hh], g_qlo[(size_t)BT * Hh];
__device__ __nv_bfloat16 g_khi[(size_t)BT * Hh], g_klo[(size_t)BT * Hh];
__device__ __nv_bfloat16 g_vhi[(size_t)BT * Hh], g_vlo[(size_t)BT * Hh];

// ---------------------------------------------------------------------------
// Helpers
// ---------------------------------------------------------------------------
__device__ __forceinline__ float fexp2(float x) {
    float z = x + 12582912.f;
    float r = x - (z - 12582912.f);
    int   e = __float_as_int(z) << 23;
    float p = 1.3333558146428443e-3f;
    p = fmaf(p, r, 9.6181291076284770e-3f);
    p = fmaf(p, r, 5.5504108664821580e-2f);
    p = fmaf(p, r, 2.4022650695910071e-1f);
    p = fmaf(p, r, 6.9314718055994531e-1f);
    p = fmaf(p, r, 1.0f);
    return __int_as_float(__float_as_int(p) + e);
}

__device__ __forceinline__ void split2(float a, float b, uint32_t& h, uint32_t& l) {
    __nv_bfloat162 hv, lv;
    hv.x = __float2bfloat16(a); hv.y = __float2bfloat16(b);
    lv.x = __float2bfloat16(a - __bfloat162float(hv.x));
    lv.y = __float2bfloat16(b - __bfloat162float(hv.y));
    h = *(uint32_t*)&hv; l = *(uint32_t*)&lv;
}

__device__ __forceinline__ uint32_t smem_u32(const void* p) {
    uint32_t a;
    asm("{ .reg .u64 t; cvta.to.shared.u64 t, %1; cvt.u32.u64 %0, t; }" : "=r"(a) : "l"(p));
    return a;
}

#define LDSM4(r, addr) \
    asm volatile("ldmatrix.sync.aligned.m8n8.x4.shared.b16 {%0,%1,%2,%3}, [%4];" \
        : "=r"((r)[0]), "=r"((r)[1]), "=r"((r)[2]), "=r"((r)[3]) : "r"(addr))
#define LDSM4T(r, addr) \
    asm volatile("ldmatrix.sync.aligned.m8n8.x4.trans.shared.b16 {%0,%1,%2,%3}, [%4];" \
        : "=r"((r)[0]), "=r"((r)[1]), "=r"((r)[2]), "=r"((r)[3]) : "r"(addr))
#define MMA16816(d, a, b0_, b1_) \
    asm volatile("mma.sync.aligned.m16n8k16.row.col.f32.bf16.bf16.f32 " \
        "{%0,%1,%2,%3}, {%4,%5,%6,%7}, {%8,%9}, {%0,%1,%2,%3};" \
        : "+f"((d)[0]), "+f"((d)[1]), "+f"((d)[2]), "+f"((d)[3]) \
        : "r"((a)[0]), "r"((a)[1]), "r"((a)[2]), "r"((a)[3]), "r"(b0_), "r"(b1_))
#define CP_ASYNC16(dst, src) \
    asm volatile("cp.async.cg.shared.global [%0], [%1], 16;" :: "r"(dst), "l"(src))
#define CP_COMMIT() asm volatile("cp.async.commit_group;" ::: "memory")
#define CP_WAIT(n)  asm volatile("cp.async.wait_group %0;" :: "n"(n) : "memory")

// ---------------------------------------------------------------------------
// Prep: split W (with Q scale folded) into bf16 hi/lo, layout [k=1024][n=192]
// ---------------------------------------------------------------------------
__global__ __launch_bounds__(256) void prep_w(
    const float* __restrict__ Wk, const float* __restrict__ Wq, const float* __restrict__ Wv)
{
    const int idx = blockIdx.x * 256 + threadIdx.x;
    const int k = idx / 192, n = idx % 192;
    float f;
    if (n < 64)       f = Wk[k * 64 + n];
    else if (n < 128) f = Wq[k * 64 + (n - 64)] * QSCALE;
    else              f = Wv[k * 64 + (n - 128)];
    __nv_bfloat16 hi = __float2bfloat16(f);
    g_Whi[idx] = hi;
    g_Wlo[idx] = __float2bfloat16(f - __bfloat162float(hi));
}

// ---------------------------------------------------------------------------
// Projection GEMM, fully pipelined: one barrier per chunk. x loaded via LDG
// into registers (prefetch distance 2), converted+STS'd after MMA issue so
// the convert runs under the HMMA drain. W cp.async double-buffered
// (prefetch distance 1, issued post-sync -> race free).
// A: swizzled 128B rows, double buffered (hi/lo). Direct register epilogue.
// ---------------------------------------------------------------------------
#define SB_OFF   65536             // A: 2 bufs x (hi 16384 + lo 16384) = 65536
#define SB_BUF   51200             // W: 2 bufs x (hi 25600 + lo 25600)
#define BSTRIDE  400
#define PJ_SMEM  167936

#define LDG_X(C0) do { \
    const float* _xs = x + (size_t)row0 * Cc + (C0) + (tid & 15) * 4; \
    _Pragma("unroll") for (int _i = 0; _i < 8; _i++) \
        xr[_i] = *(const float4*)(_xs + (size_t)(_i * 16 + (tid >> 4)) * Cc); \
} while (0)

#define CONVERT_X(P) do { \
    _Pragma("unroll") for (int _i = 0; _i < 8; _i++) { \
        const int _r = _i * 16 + (tid >> 4); \
        const int _c4 = tid & 15; \
        uint2 _hv, _lv; \
        split2(xr[_i].x, xr[_i].y, _hv.x, _lv.x); \
        split2(xr[_i].z, xr[_i].w, _hv.y, _lv.y); \
        const uint32_t _off = (uint32_t)(_r * 128 + (((_c4 >> 1) ^ (_r & 7)) << 4) + (_c4 & 1) * 8); \
        *(uint2*)(smp + (P) * 32768 + _off) = _hv; \
        *(uint2*)(smp + (P) * 32768 + 16384 + _off) = _lv; \
    } \
} while (0)

#define W_LOAD(C) do { \
    const uint32_t _bw = sb + SB_OFF + ((C) & 1) * SB_BUF; \
    _Pragma("unroll") for (int _i = 0; _i < 6; _i++) { \
        const int _u = _i * 256 + tid; \
        const int _r = _u / 24, _cg = _u % 24; \
        const uint32_t _d = _bw + _r * BSTRIDE + _cg * 16; \
        const size_t _s = (size_t)((C) * 64 + _r) * 192 + _cg * 8; \
        CP_ASYNC16(_d,         (const char*)(g_Whi + _s)); \
        CP_ASYNC16(_d + 25600, (const char*)(g_Wlo + _s)); \
    } \
    CP_COMMIT(); \
} while (0)

__global__ __launch_bounds__(256, 1) void proj_tc(const float* __restrict__ x)
{
    extern __shared__ char smp[];
    const uint32_t sb = smem_u32(smp);
    const int tid  = threadIdx.x;
    const int wid  = tid >> 5;
    const int lane = tid & 31;
    const int wm   = wid >> 1;
    const int wn   = wid & 1;
    const int row0 = blockIdx.x * 128;

    const int gid = lane >> 2, tig = lane & 3;
    const int lr  = lane & 7,  grp = lane >> 3;

    float acc[2][12][4];
#pragma unroll
    for (int mi = 0; mi < 2; mi++)
#pragma unroll
        for (int j = 0; j < 12; j++)
#pragma unroll
            for (int e = 0; e < 4; e++) acc[mi][j][e] = 0.f;

    int rowA[2];
#pragma unroll
    for (int mi = 0; mi < 2; mi++) rowA[mi] = wm * 32 + mi * 16 + lr + (grp & 1) * 8;
    const int ac16g = grp >> 1;
    const uint32_t bofs = (uint32_t)((lr + (grp & 1) * 8) * BSTRIDE + wn * 192 + (grp >> 1) * 16);

    float4 xr[8];

    // ---- prologue: x(0)->A buf0 (regs->smem), W(0) in flight, x(1) in regs ----
    LDG_X(0);
    W_LOAD(0);
    CONVERT_X(0);
    LDG_X(64);

    for (int c = 0; c < 16; c++) {
        const int p = c & 1;
        CP_WAIT(0);                 // W(c) landed
        __syncthreads();            // A(c) STS (from iter c-1) visible to all

        // ---- MMA(c): issue the full tensor batch first ----
        const uint32_t abh  = sb + p * 32768;
        const uint32_t abl  = abh + 16384;
        const uint32_t bbuf = sb + SB_OFF + p * SB_BUF;
#pragma unroll
        for (int ks = 0; ks < 4; ks++) {
            uint32_t ah[2][4], al[2][4];
#pragma unroll
            for (int mi = 0; mi < 2; mi++) {
                const int c16 = 2 * ks + ac16g;
                const uint32_t aoff = (uint32_t)(rowA[mi] * 128 + ((c16 ^ lr) << 4));
                LDSM4(ah[mi], abh + aoff);
                LDSM4(al[mi], abl + aoff);
            }
#pragma unroll
            for (int nt = 0; nt < 6; nt++) {
                uint32_t bh[4], bl[4];
                const uint32_t ba = bbuf + bofs + (uint32_t)(ks * 16 * BSTRIDE + nt * 32);
                LDSM4T(bh, ba);
                LDSM4T(bl, ba + 25600);
#pragma unroll
                for (int mi = 0; mi < 2; mi++) {
                    MMA16816(acc[mi][2 * nt],     ah[mi], bh[0], bh[1]);
                    MMA16816(acc[mi][2 * nt],     ah[mi], bl[0], bl[1]);
                    MMA16816(acc[mi][2 * nt],     al[mi], bh[0], bh[1]);
                    MMA16816(acc[mi][2 * nt + 1], ah[mi], bh[2], bh[3]);
                    MMA16816(acc[mi][2 * nt + 1], ah[mi], bl[2], bl[3]);
                    MMA16816(acc[mi][2 * nt + 1], al[mi], bh[2], bh[3]);
                }
            }
        }

        // ---- under the HMMA drain: W(c+1), convert x(c+1), LDG x(c+2) ----
        if (c < 15) {
            W_LOAD(c + 1);
            CONVERT_X(p ^ 1);
        }
        if (c < 14) LDG_X((c + 2) * 64);
    }

    // ---- epilogue: direct register -> global bf16 hi/lo ----
#pragma unroll
    for (int mi = 0; mi < 2; mi++) {
        const int r1 = row0 + wm * 32 + mi * 16 + gid;
        const int r2 = r1 + 8;
#pragma unroll
        for (int j = 0; j < 12; j++) {
            const int col = wn * 96 + j * 8 + tig * 2;
            __nv_bfloat16 *dh, *dl; int cc;
            if (col < 64)       { dh = g_khi; dl = g_klo; cc = col; }
            else if (col < 128) { dh = g_qhi; dl = g_qlo; cc = col - 64; }
            else                { dh = g_vhi; dl = g_vlo; cc = col - 128; }
            uint32_t h1, l1, h2, l2;
            split2(acc[mi][j][0], acc[mi][j][1], h1, l1);
            split2(acc[mi][j][2], acc[mi][j][3], h2, l2);
            *(uint32_t*)(dh + (size_t)r1 * Hh + cc) = h1;
            *(uint32_t*)(dl + (size_t)r1 * Hh + cc) = l1;
            *(uint32_t*)(dh + (size_t)r2 * Hh + cc) = h2;
            *(uint32_t*)(dl + (size_t)r2 * Hh + cc) = l2;
        }
    }
}

// ---------------------------------------------------------------------------
// Flash attention, software-pipelined FA2: per iteration, S-MMA(j) is issued
// FIRST (tensor pipe), then softmax+PV of tile j-1 run behind it (fma pipe
// overlaps the HMMA drain). KV in a 3-stage cp.async ring (V(j-1) must
// survive the KV(j+1) prefetch). One __syncthreads per iteration.
// ---------------------------------------------------------------------------
#define RSTRIDE 144
#define QH_OFF  0
#define QL_OFF  18432
#define KV_OFF  36864
#define KVBUF   36864
#define AT_SMEM 147456            // Q(2x18432) + 3 x KVBUF

#define LOAD_KV(J) do { \
    const int _jn = (J) * 64; \
    const uint32_t _bufn = sb + KV_OFF + ((J) % 3) * KVBUF; \
    _Pragma("unroll") for (int _i = 0; _i < 2; _i++) { \
        const int _idx = _i * 256 + tid; \
        const int _r = _idx >> 3, _cg = _idx & 7; \
        const size_t _g = (size_t)(b * Tt + _jn + _r) * Hh + _cg * 8; \
        const uint32_t _d0 = _bufn + _r * RSTRIDE + _cg * 16; \
        CP_ASYNC16(_d0,         (const char*)(g_khi + _g)); \
        CP_ASYNC16(_d0 + 9216,  (const char*)(g_klo + _g)); \
        CP_ASYNC16(_d0 + 18432, (const char*)(g_vhi + _g)); \
        CP_ASYNC16(_d0 + 27648, (const char*)(g_vlo + _g)); \
    } \
    CP_COMMIT(); \
} while (0)

#define ATTN_S(J, SN) do { \
    const uint32_t _buf = sb + KV_OFF + ((J) % 3) * KVBUF; \
    _Pragma("unroll") for (int _nt = 0; _nt < 8; _nt++) \
        _Pragma("unroll") for (int _e = 0; _e < 4; _e++) SN[_nt][_e] = 0.f; \
    _Pragma("unroll") for (int _ks = 0; _ks < 4; _ks++) { \
        uint32_t _qh[4], _ql[4]; \
        LDSM4(_qh, sQh + aQ + _ks * 32); \
        LDSM4(_ql, sQl + aQ + _ks * 32); \
        _Pragma("unroll") for (int _np = 0; _np < 4; _np++) { \
            uint32_t _bh[4], _bl[4]; \
            const uint32_t _ka = _buf + aK + _np * (16 * RSTRIDE) + _ks * 32; \
            LDSM4(_bh, _ka); \
            LDSM4(_bl, _ka + 9216); \
            MMA16816(SN[2 * _np],     _qh, _bh[0], _bh[1]); \
            MMA16816(SN[2 * _np],     _qh, _bl[0], _bl[1]); \
            MMA16816(SN[2 * _np],     _ql, _bh[0], _bh[1]); \
            MMA16816(SN[2 * _np + 1], _qh, _bh[2], _bh[3]); \
            MMA16816(SN[2 * _np + 1], _qh, _bl[2], _bl[3]); \
            MMA16816(SN[2 * _np + 1], _ql, _bh[2], _bh[3]); \
        } \
    } \
} while (0)

#define ATTN_SMAX_PV(JP, SP) do { \
    const int _j0p = (JP) * 64; \
    const uint32_t _bufv = sb + KV_OFF + ((JP) % 3) * KVBUF + 18432; \
    if (_j0p + 63 > q0 + 16 * w) { \
        _Pragma("unroll") for (int _nt = 0; _nt < 8; _nt++) { \
            const int _cb = _j0p + 8 * _nt + 2 * tig; \
            if (_cb     > r1g) SP[_nt][0] = -1e30f; \
            if (_cb + 1 > r1g) SP[_nt][1] = -1e30f; \
            if (_cb     > r2g) SP[_nt][2] = -1e30f; \
            if (_cb + 1 > r2g) SP[_nt][3] = -1e30f; \
        } \
    } \
    float _mx0 = SP[0][0], _mx1 = SP[0][2]; \
    _Pragma("unroll") for (int _nt = 0; _nt < 8; _nt++) { \
        _mx0 = fmaxf(_mx0, fmaxf(SP[_nt][0], SP[_nt][1])); \
        _mx1 = fmaxf(_mx1, fmaxf(SP[_nt][2], SP[_nt][3])); \
    } \
    _mx0 = fmaxf(_mx0, __shfl_xor_sync(0xffffffffu, _mx0, 1)); \
    _mx0 = fmaxf(_mx0, __shfl_xor_sync(0xffffffffu, _mx0, 2)); \
    _mx1 = fmaxf(_mx1, __shfl_xor_sync(0xffffffffu, _mx1, 1)); \
    _mx1 = fmaxf(_mx1, __shfl_xor_sync(0xffffffffu, _mx1, 2)); \
    const float _mn0 = fmaxf(m0, _mx0), _mn1 = fmaxf(m1, _mx1); \
    const float _a0 = fexp2(fmaxf(m0 - _mn0, -125.f)); \
    const float _a1 = fexp2(fmaxf(m1 - _mn1, -125.f)); \
    float _sm0 = 0.f, _sm1 = 0.f; \
    _Pragma("unroll") for (int _nt = 0; _nt < 8; _nt++) { \
        SP[_nt][0] = fexp2(fmaxf(SP[_nt][0] - _mn0, -125.f)); \
        SP[_nt][1] = fexp2(fmaxf(SP[_nt][1] - _mn0, -125.f)); \
        SP[_nt][2] = fexp2(fmaxf(SP[_nt][2] - _mn1, -125.f)); \
        SP[_nt][3] = fexp2(fmaxf(SP[_nt][3] - _mn1, -125.f)); \
        _sm0 += SP[_nt][0] + SP[_nt][1]; \
        _sm1 += SP[_nt][2] + SP[_nt][3]; \
    } \
    _sm0 += __shfl_xor_sync(0xffffffffu, _sm0, 1); \
    _sm0 += __shfl_xor_sync(0xffffffffu, _sm0, 2); \
    _sm1 += __shfl_xor_sync(0xffffffffu, _sm1, 1); \
    _sm1 += __shfl_xor_sync(0xffffffffu, _sm1, 2); \
    l0 = l0 * _a0 + _sm0; \
    l1 = l1 * _a1 + _sm1; \
    m0 = _mn0; m1 = _mn1; \
    _Pragma("unroll") for (int _nt = 0; _nt < 8; _nt++) { \
        o[_nt][0] *= _a0; o[_nt][1] *= _a0; \
        o[_nt][2] *= _a1; o[_nt][3] *= _a1; \
    } \
    _Pragma("unroll") for (int _kt = 0; _kt < 4; _kt++) { \
        uint32_t _ah[4], _al[4]; \
        split2(SP[2 * _kt][0],     SP[2 * _kt][1],     _ah[0], _al[0]); \
        split2(SP[2 * _kt][2],     SP[2 * _kt][3],     _ah[1], _al[1]); \
        split2(SP[2 * _kt + 1][0], SP[2 * _kt + 1][1], _ah[2], _al[2]); \
        split2(SP[2 * _kt + 1][2], SP[2 * _kt + 1][3], _ah[3], _al[3]); \
        _Pragma("unroll") for (int _nh = 0; _nh < 4; _nh++) { \
            uint32_t _bh[4], _bl[4]; \
            const uint32_t _va = _bufv + aV + _kt * (16 * RSTRIDE) + _nh * 32; \
            LDSM4T(_bh, _va); \
            LDSM4T(_bl, _va + 9216); \
            MMA16816(o[2 * _nh],     _ah, _bh[0], _bh[1]); \
            MMA16816(o[2 * _nh],     _ah, _bl[0], _bl[1]); \
            MMA16816(o[2 * _nh],     _al, _bh[0], _bh[1]); \
            MMA16816(o[2 * _nh + 1], _ah, _bh[2], _bh[3]); \
            MMA16816(o[2 * _nh + 1], _ah, _bl[2], _bl[3]); \
            MMA16816(o[2 * _nh + 1], _al, _bh[2], _bh[3]); \
        } \
    } \
} while (0)

#define ATTN_STEP(J, SN, SP) do { \
    CP_WAIT(0); \
    __syncthreads(); \
    if ((J) <= jmax && (J) * 64 <= q0 + 16 * w + 15) ATTN_S(J, SN); \
    if ((J) < jmax) LOAD_KV((J) + 1); \
    if ((J) >= 1 && ((J) - 1) * 64 <= q0 + 16 * w + 15) ATTN_SMAX_PV((J) - 1, SP); \
} while (0)

__global__ __launch_bounds__(256, 1) void attn_tc(float* __restrict__ out)
{
    extern __shared__ char sma[];
    const uint32_t sb  = smem_u32(sma);
    const uint32_t sQh = sb + QH_OFF;
    const uint32_t sQl = sb + QL_OFF;

    const int tid  = threadIdx.x;
    const int w    = tid >> 5;
    const int lane = tid & 31;
    const int b    = blockIdx.y;
    const int it   = (Tt / 128 - 1) - blockIdx.x;    // heaviest tiles first
    const int q0   = it * 128;
    const int jmax = 2 * it + 1;                     // odd

    const int gid = lane >> 2, tig = lane & 3;
    const int lr  = lane & 7,  grp = lane >> 3;

    const uint32_t aQ = (uint32_t)((16 * w + lr + (grp & 1) * 8) * RSTRIDE + (grp >> 1) * 16);
    const uint32_t aK = (uint32_t)((lr + (grp >> 1) * 8) * RSTRIDE + (grp & 1) * 16);
    const uint32_t aV = (uint32_t)((lr + (grp & 1) * 8) * RSTRIDE + (grp >> 1) * 16);

    // ---- prologue: Q (hi/lo) + KV(0), one commit group ----
#pragma unroll
    for (int i = 0; i < 4; i++) {
        const int idx = i * 256 + tid;
        const int r = idx >> 3, cg = idx & 7;
        const size_t g = (size_t)(b * Tt + q0 + r) * Hh + cg * 8;
        CP_ASYNC16(sQh + r * RSTRIDE + cg * 16, (const char*)(g_qhi + g));
        CP_ASYNC16(sQl + r * RSTRIDE + cg * 16, (const char*)(g_qlo + g));
    }
#pragma unroll
    for (int i = 0; i < 2; i++) {
        const int idx = i * 256 + tid;
        const int r = idx >> 3, cg = idx & 7;
        const size_t g = (size_t)(b * Tt + r) * Hh + cg * 8;
        const uint32_t d0 = sb + KV_OFF + r * RSTRIDE + cg * 16;
        CP_ASYNC16(d0,         (const char*)(g_khi + g));
        CP_ASYNC16(d0 + 9216,  (const char*)(g_klo + g));
        CP_ASYNC16(d0 + 18432, (const char*)(g_vhi + g));
        CP_ASYNC16(d0 + 27648, (const char*)(g_vlo + g));
    }
    CP_COMMIT();

    float o[8][4];
#pragma unroll
    for (int nt = 0; nt < 8; nt++)
#pragma unroll
        for (int e = 0; e < 4; e++) o[nt][e] = 0.f;
    float m0 = -1e30f, m1 = -1e30f, l0 = 0.f, l1 = 0.f;
    float s0[8][4], s1[8][4];

    const int r1g = q0 + 16 * w + gid;
    const int r2g = r1g + 8;

    // ---- pipelined main loop: steps 0..jmax, then tail step jmax+1 ----
    for (int j = 0; j <= jmax; j += 2) {
        ATTN_STEP(j,     s0, s1);
        ATTN_STEP(j + 1, s1, s0);
    }
    ATTN_STEP(jmax + 1, s0, s1);     // drains softmax+PV of tile jmax (in s1)

    // ---- normalize + write ----
    const float inv0 = 1.f / l0, inv1 = 1.f / l1;
    float* o1 = out + ((size_t)b * Tt + r1g) * Hh + 2 * tig;
    float* o2 = out + ((size_t)b * Tt + r2g) * Hh + 2 * tig;
#pragma unroll
    for (int nt = 0; nt < 8; nt++) {
        *(float2*)(o1 + 8 * nt) = make_float2(o[nt][0] * inv0, o[nt][1] * inv0);
        *(float2*)(o2 + 8 * nt) = make_float2(o[nt][2] * inv1, o[nt][3] * inv1);
    }
}

// ---------------------------------------------------------------------------
// Harness entry
// ---------------------------------------------------------------------------
extern "C" void kernel_launch(void* const* d_in, const int* in_sizes, int n_in,
                              void* d_out, int out_size)
{
    const float* x  = (const float*)d_in[0];
    const float* Wk = (const float*)d_in[1];
    const float* Wq = (const float*)d_in[2];
    const float* Wv = (const float*)d_in[3];
    float* out = (float*)d_out;

    cudaFuncSetAttribute(proj_tc, cudaFuncAttributeMaxDynamicSharedMemorySize, PJ_SMEM);
    cudaFuncSetAttribute(attn_tc, cudaFuncAttributeMaxDynamicSharedMemorySize, AT_SMEM);

    prep_w<<<768, 256>>>(Wk, Wq, Wv);
    proj_tc<<<BT / 128, 256, PJ_SMEM>>>(x);
    attn_tc<<<dim3(Tt / 128, Bb), 256, AT_SMEM>>>(out);
}

// round 7
// speedup vs baseline: 4.4243x; 1.5931x over previous
#include <cuda_runtime.h>
#include <cuda_fp16.h>
#include <cstdint>

// Problem constants
#define Bb 32
#define Tt 2048
#define Cc 1024
#define Hh 64
#define BT (Bb * Tt)

// 0.125 (= H^-0.5) * log2(e): scores computed directly in base-2 domain
#define QSCALE 0.180336880111227f

// Scratch (__device__ globals; no allocation allowed)
__device__ __half g_Wh[(size_t)Cc * 192];     // [k][n]  n: 0..63 K, 64..127 Q, 128..191 V
__device__ __half g_q[(size_t)BT * Hh];
__device__ __half g_k[(size_t)BT * Hh];
__device__ __half g_v[(size_t)BT * Hh];

// ---------------------------------------------------------------------------
// Helpers
// ---------------------------------------------------------------------------
__device__ __forceinline__ float fexp2(float x) {
    float z = x + 12582912.f;
    float r = x - (z - 12582912.f);
    int   e = __float_as_int(z) << 23;
    float p = 1.3333558146428443e-3f;
    p = fmaf(p, r, 9.6181291076284770e-3f);
    p = fmaf(p, r, 5.5504108664821580e-2f);
    p = fmaf(p, r, 2.4022650695910071e-1f);
    p = fmaf(p, r, 6.9314718055994531e-1f);
    p = fmaf(p, r, 1.0f);
    return __int_as_float(__float_as_int(p) + e);
}

__device__ __forceinline__ uint32_t pk(float a, float b) {
    __half2 h = __floats2half2_rn(a, b);
    return *(uint32_t*)&h;
}

__device__ __forceinline__ uint32_t smem_u32(const void* p) {
    uint32_t a;
    asm("{ .reg .u64 t; cvta.to.shared.u64 t, %1; cvt.u32.u64 %0, t; }" : "=r"(a) : "l"(p));
    return a;
}

#define LDSM4(r, addr) \
    asm volatile("ldmatrix.sync.aligned.m8n8.x4.shared.b16 {%0,%1,%2,%3}, [%4];" \
        : "=r"((r)[0]), "=r"((r)[1]), "=r"((r)[2]), "=r"((r)[3]) : "r"(addr))
#define LDSM4T(r, addr) \
    asm volatile("ldmatrix.sync.aligned.m8n8.x4.trans.shared.b16 {%0,%1,%2,%3}, [%4];" \
        : "=r"((r)[0]), "=r"((r)[1]), "=r"((r)[2]), "=r"((r)[3]) : "r"(addr))
#define MMAH(d, a, b0_, b1_) \
    asm volatile("mma.sync.aligned.m16n8k16.row.col.f32.f16.f16.f32 " \
        "{%0,%1,%2,%3}, {%4,%5,%6,%7}, {%8,%9}, {%0,%1,%2,%3};" \
        : "+f"((d)[0]), "+f"((d)[1]), "+f"((d)[2]), "+f"((d)[3]) \
        : "r"((a)[0]), "r"((a)[1]), "r"((a)[2]), "r"((a)[3]), "r"(b0_), "r"(b1_))
#define CP_ASYNC16(dst, src) \
    asm volatile("cp.async.cg.shared.global [%0], [%1], 16;" :: "r"(dst), "l"(src))
#define CP_COMMIT() asm volatile("cp.async.commit_group;" ::: "memory")
#define CP_WAIT(n)  asm volatile("cp.async.wait_group %0;" :: "n"(n) : "memory")

// ---------------------------------------------------------------------------
// Prep: W -> fp16, Q scale folded, layout [k=1024][n=192]
// ---------------------------------------------------------------------------
__global__ __launch_bounds__(256) void prep_w(
    const float* __restrict__ Wk, const float* __restrict__ Wq, const float* __restrict__ Wv)
{
    const int idx = blockIdx.x * 256 + threadIdx.x;
    const int k = idx / 192, n = idx % 192;
    float f;
    if (n < 64)       f = Wk[k * 64 + n];
    else if (n < 128) f = Wq[k * 64 + (n - 64)] * QSCALE;
    else              f = Wv[k * 64 + (n - 128)];
    g_Wh[idx] = __float2half_rn(f);
}

// ---------------------------------------------------------------------------
// Projection GEMM, fp16 single-term, fully pipelined (one barrier per chunk).
// x LDG->regs (distance 2), convert+STS under the HMMA drain; W cp.async
// double-buffered. A swizzled 128B rows. Direct register epilogue.
// ---------------------------------------------------------------------------
#define SB_OFF   32768             // A: 2 bufs x 16384
#define SB_BUF   25600             // W: 2 bufs x (64 rows x 400B)
#define BSTRIDE  400
#define PJ_SMEM  83968

#define LDG_X(C0) do { \
    const float* _xs = x + (size_t)row0 * Cc + (C0) + (tid & 15) * 4; \
    _Pragma("unroll") for (int _i = 0; _i < 8; _i++) \
        xr[_i] = *(const float4*)(_xs + (size_t)(_i * 16 + (tid >> 4)) * Cc); \
} while (0)

#define CONVERT_X(P) do { \
    _Pragma("unroll") for (int _i = 0; _i < 8; _i++) { \
        const int _r = _i * 16 + (tid >> 4); \
        const int _c4 = tid & 15; \
        uint2 _hv; \
        _hv.x = pk(xr[_i].x, xr[_i].y); \
        _hv.y = pk(xr[_i].z, xr[_i].w); \
        const uint32_t _off = (uint32_t)(_r * 128 + (((_c4 >> 1) ^ (_r & 7)) << 4) + (_c4 & 1) * 8); \
        *(uint2*)(smp + (P) * 16384 + _off) = _hv; \
    } \
} while (0)

#define W_LOAD(C) do { \
    const uint32_t _bw = sb + SB_OFF + ((C) & 1) * SB_BUF; \
    _Pragma("unroll") for (int _i = 0; _i < 6; _i++) { \
        const int _u = _i * 256 + tid; \
        const int _r = _u / 24, _cg = _u % 24; \
        CP_ASYNC16(_bw + _r * BSTRIDE + _cg * 16, \
                   (const char*)(g_Wh + (size_t)((C) * 64 + _r) * 192 + _cg * 8)); \
    } \
    CP_COMMIT(); \
} while (0)

__global__ __launch_bounds__(256) void proj_tc(const float* __restrict__ x)
{
    extern __shared__ char smp[];
    const uint32_t sb = smem_u32(smp);
    const int tid  = threadIdx.x;
    const int wid  = tid >> 5;
    const int lane = tid & 31;
    const int wm   = wid >> 1;
    const int wn   = wid & 1;
    const int row0 = blockIdx.x * 128;

    const int gid = lane >> 2, tig = lane & 3;
    const int lr  = lane & 7,  grp = lane >> 3;

    float acc[2][12][4];
#pragma unroll
    for (int mi = 0; mi < 2; mi++)
#pragma unroll
        for (int j = 0; j < 12; j++)
#pragma unroll
            for (int e = 0; e < 4; e++) acc[mi][j][e] = 0.f;

    int rowA[2];
#pragma unroll
    for (int mi = 0; mi < 2; mi++) rowA[mi] = wm * 32 + mi * 16 + lr + (grp & 1) * 8;
    const int ac16g = grp >> 1;
    const uint32_t bofs = (uint32_t)((lr + (grp & 1) * 8) * BSTRIDE + wn * 192 + (grp >> 1) * 16);

    float4 xr[8];

    // ---- prologue ----
    LDG_X(0);
    W_LOAD(0);
    CONVERT_X(0);
    LDG_X(64);

    for (int c = 0; c < 16; c++) {
        const int p = c & 1;
        CP_WAIT(0);                 // W(c) landed
        __syncthreads();            // A(c) STS visible

        // ---- MMA(c) ----
        const uint32_t abh  = sb + p * 16384;
        const uint32_t bbuf = sb + SB_OFF + p * SB_BUF;
#pragma unroll
        for (int ks = 0; ks < 4; ks++) {
            uint32_t ah[2][4];
#pragma unroll
            for (int mi = 0; mi < 2; mi++) {
                const int c16 = 2 * ks + ac16g;
                LDSM4(ah[mi], abh + (uint32_t)(rowA[mi] * 128 + ((c16 ^ lr) << 4)));
            }
#pragma unroll
            for (int nt = 0; nt < 6; nt++) {
                uint32_t bh[4];
                LDSM4T(bh, bbuf + bofs + (uint32_t)(ks * 16 * BSTRIDE + nt * 32));
#pragma unroll
                for (int mi = 0; mi < 2; mi++) {
                    MMAH(acc[mi][2 * nt],     ah[mi], bh[0], bh[1]);
                    MMAH(acc[mi][2 * nt + 1], ah[mi], bh[2], bh[3]);
                }
            }
        }

        // ---- under the HMMA drain ----
        if (c < 15) {
            W_LOAD(c + 1);
            CONVERT_X(p ^ 1);
        }
        if (c < 14) LDG_X((c + 2) * 64);
    }

    // ---- epilogue: direct register -> global fp16 ----
#pragma unroll
    for (int mi = 0; mi < 2; mi++) {
        const int r1 = row0 + wm * 32 + mi * 16 + gid;
        const int r2 = r1 + 8;
#pragma unroll
        for (int j = 0; j < 12; j++) {
            const int col = wn * 96 + j * 8 + tig * 2;
            __half* dst; int cc;
            if (col < 64)       { dst = g_k; cc = col; }
            else if (col < 128) { dst = g_q; cc = col - 64; }
            else                { dst = g_v; cc = col - 128; }
            *(uint32_t*)(dst + (size_t)r1 * Hh + cc) = pk(acc[mi][j][0], acc[mi][j][1]);
            *(uint32_t*)(dst + (size_t)r2 * Hh + cc) = pk(acc[mi][j][2], acc[mi][j][3]);
        }
    }
}

// ---------------------------------------------------------------------------
// Flash attention, fp16 single-term, software-pipelined: S-MMA(j) issued
// first, softmax+PV(j-1) behind it. 3-stage KV ring, 2 CTAs/SM.
// ---------------------------------------------------------------------------
#define RSTRIDE 144
#define KV_OFF  18432             // Q: 128 rows x 144
#define KVBUF   18432             // K 9216 + V 9216
#define AT_SMEM 73728             // Q + 3 x KVBUF

#define LOAD_KV(J) do { \
    const int _jn = (J) * 64; \
    const uint32_t _bufn = sb + KV_OFF + ((J) % 3) * KVBUF; \
    _Pragma("unroll") for (int _i = 0; _i < 2; _i++) { \
        const int _idx = _i * 256 + tid; \
        const int _r = _idx >> 3, _cg = _idx & 7; \
        const size_t _g = (size_t)(b * Tt + _jn + _r) * Hh + _cg * 8; \
        const uint32_t _d0 = _bufn + _r * RSTRIDE + _cg * 16; \
        CP_ASYNC16(_d0,        (const char*)(g_k + _g)); \
        CP_ASYNC16(_d0 + 9216, (const char*)(g_v + _g)); \
    } \
    CP_COMMIT(); \
} while (0)

#define ATTN_S(J, SN) do { \
    const uint32_t _buf = sb + KV_OFF + ((J) % 3) * KVBUF; \
    _Pragma("unroll") for (int _nt = 0; _nt < 8; _nt++) \
        _Pragma("unroll") for (int _e = 0; _e < 4; _e++) SN[_nt][_e] = 0.f; \
    _Pragma("unroll") for (int _ks = 0; _ks < 4; _ks++) { \
        uint32_t _qh[4]; \
        LDSM4(_qh, sQh + aQ + _ks * 32); \
        _Pragma("unroll") for (int _np = 0; _np < 4; _np++) { \
            uint32_t _bh[4]; \
            LDSM4(_bh, _buf + aK + _np * (16 * RSTRIDE) + _ks * 32); \
            MMAH(SN[2 * _np],     _qh, _bh[0], _bh[1]); \
            MMAH(SN[2 * _np + 1], _qh, _bh[2], _bh[3]); \
        } \
    } \
} while (0)

#define ATTN_SMAX_PV(JP, SP) do { \
    const int _j0p = (JP) * 64; \
    const uint32_t _bufv = sb + KV_OFF + ((JP) % 3) * KVBUF + 9216; \
    if (_j0p + 63 > q0 + 16 * w) { \
        _Pragma("unroll") for (int _nt = 0; _nt < 8; _nt++) { \
            const int _cb = _j0p + 8 * _nt + 2 * tig; \
            if (_cb     > r1g) SP[_nt][0] = -1e30f; \
            if (_cb + 1 > r1g) SP[_nt][1] = -1e30f; \
            if (_cb     > r2g) SP[_nt][2] = -1e30f; \
            if (_cb + 1 > r2g) SP[_nt][3] = -1e30f; \
        } \
    } \
    float _mx0 = SP[0][0], _mx1 = SP[0][2]; \
    _Pragma("unroll") for (int _nt = 0; _nt < 8; _nt++) { \
        _mx0 = fmaxf(_mx0, fmaxf(SP[_nt][0], SP[_nt][1])); \
        _mx1 = fmaxf(_mx1, fmaxf(SP[_nt][2], SP[_nt][3])); \
    } \
    _mx0 = fmaxf(_mx0, __shfl_xor_sync(0xffffffffu, _mx0, 1)); \
    _mx0 = fmaxf(_mx0, __shfl_xor_sync(0xffffffffu, _mx0, 2)); \
    _mx1 = fmaxf(_mx1, __shfl_xor_sync(0xffffffffu, _mx1, 1)); \
    _mx1 = fmaxf(_mx1, __shfl_xor_sync(0xffffffffu, _mx1, 2)); \
    const float _mn0 = fmaxf(m0, _mx0), _mn1 = fmaxf(m1, _mx1); \
    const float _a0 = fexp2(fmaxf(m0 - _mn0, -125.f)); \
    const float _a1 = fexp2(fmaxf(m1 - _mn1, -125.f)); \
    float _sm0 = 0.f, _sm1 = 0.f; \
    _Pragma("unroll") for (int _nt = 0; _nt < 8; _nt++) { \
        SP[_nt][0] = fexp2(fmaxf(SP[_nt][0] - _mn0, -125.f)); \
        SP[_nt][1] = fexp2(fmaxf(SP[_nt][1] - _mn0, -125.f)); \
        SP[_nt][2] = fexp2(fmaxf(SP[_nt][2] - _mn1, -125.f)); \
        SP[_nt][3] = fexp2(fmaxf(SP[_nt][3] - _mn1, -125.f)); \
        _sm0 += SP[_nt][0] + SP[_nt][1]; \
        _sm1 += SP[_nt][2] + SP[_nt][3]; \
    } \
    _sm0 += __shfl_xor_sync(0xffffffffu, _sm0, 1); \
    _sm0 += __shfl_xor_sync(0xffffffffu, _sm0, 2); \
    _sm1 += __shfl_xor_sync(0xffffffffu, _sm1, 1); \
    _sm1 += __shfl_xor_sync(0xffffffffu, _sm1, 2); \
    l0 = l0 * _a0 + _sm0; \
    l1 = l1 * _a1 + _sm1; \
    m0 = _mn0; m1 = _mn1; \
    _Pragma("unroll") for (int _nt = 0; _nt < 8; _nt++) { \
        o[_nt][0] *= _a0; o[_nt][1] *= _a0; \
        o[_nt][2] *= _a1; o[_nt][3] *= _a1; \
    } \
    _Pragma("unroll") for (int _kt = 0; _kt < 4; _kt++) { \
        uint32_t _ah[4]; \
        _ah[0] = pk(SP[2 * _kt][0],     SP[2 * _kt][1]); \
        _ah[1] = pk(SP[2 * _kt][2],     SP[2 * _kt][3]); \
        _ah[2] = pk(SP[2 * _kt + 1][0], SP[2 * _kt + 1][1]); \
        _ah[3] = pk(SP[2 * _kt + 1][2], SP[2 * _kt + 1][3]); \
        _Pragma("unroll") for (int _nh = 0; _nh < 4; _nh++) { \
            uint32_t _bh[4]; \
            LDSM4T(_bh, _bufv + aV + _kt * (16 * RSTRIDE) + _nh * 32); \
            MMAH(o[2 * _nh],     _ah, _bh[0], _bh[1]); \
            MMAH(o[2 * _nh + 1], _ah, _bh[2], _bh[3]); \
        } \
    } \
} while (0)

#define ATTN_STEP(J, SN, SP) do { \
    CP_WAIT(0); \
    __syncthreads(); \
    if ((J) <= jmax && (J) * 64 <= q0 + 16 * w + 15) ATTN_S(J, SN); \
    if ((J) < jmax) LOAD_KV((J) + 1); \
    if ((J) >= 1 && ((J) - 1) * 64 <= q0 + 16 * w + 15) ATTN_SMAX_PV((J) - 1, SP); \
} while (0)

__global__ __launch_bounds__(256, 2) void attn_tc(float* __restrict__ out)
{
    extern __shared__ char sma[];
    const uint32_t sb  = smem_u32(sma);
    const uint32_t sQh = sb;

    const int tid  = threadIdx.x;
    const int w    = tid >> 5;
    const int lane = tid & 31;
    const int b    = blockIdx.y;
    const int it   = (Tt / 128 - 1) - blockIdx.x;    // heaviest tiles first
    const int q0   = it * 128;
    const int jmax = 2 * it + 1;

    const int gid = lane >> 2, tig = lane & 3;
    const int lr  = lane & 7,  grp = lane >> 3;

    const uint32_t aQ = (uint32_t)((16 * w + lr + (grp & 1) * 8) * RSTRIDE + (grp >> 1) * 16);
    const uint32_t aK = (uint32_t)((lr + (grp >> 1) * 8) * RSTRIDE + (grp & 1) * 16);
    const uint32_t aV = (uint32_t)((lr + (grp & 1) * 8) * RSTRIDE + (grp >> 1) * 16);

    // ---- prologue: Q + KV(0) ----
#pragma unroll
    for (int i = 0; i < 4; i++) {
        const int idx = i * 256 + tid;
        const int r = idx >> 3, cg = idx & 7;
        CP_ASYNC16(sQh + r * RSTRIDE + cg * 16,
                   (const char*)(g_q + (size_t)(b * Tt + q0 + r) * Hh + cg * 8));
    }
#pragma unroll
    for (int i = 0; i < 2; i++) {
        const int idx = i * 256 + tid;
        const int r = idx >> 3, cg = idx & 7;
        const size_t g = (size_t)(b * Tt + r) * Hh + cg * 8;
        const uint32_t d0 = sb + KV_OFF + r * RSTRIDE + cg * 16;
        CP_ASYNC16(d0,        (const char*)(g_k + g));
        CP_ASYNC16(d0 + 9216, (const char*)(g_v + g));
    }
    CP_COMMIT();

    float o[8][4];
#pragma unroll
    for (int nt = 0; nt < 8; nt++)
#pragma unroll
        for (int e = 0; e < 4; e++) o[nt][e] = 0.f;
    float m0 = -1e30f, m1 = -1e30f, l0 = 0.f, l1 = 0.f;
    float s0[8][4], s1[8][4];

    const int r1g = q0 + 16 * w + gid;
    const int r2g = r1g + 8;

    // ---- pipelined main loop + tail ----
    for (int j = 0; j <= jmax; j += 2) {
        ATTN_STEP(j,     s0, s1);
        ATTN_STEP(j + 1, s1, s0);
    }
    ATTN_STEP(jmax + 1, s0, s1);

    // ---- normalize + write ----
    const float inv0 = 1.f / l0, inv1 = 1.f / l1;
    float* o1 = out + ((size_t)b * Tt + r1g) * Hh + 2 * tig;
    float* o2 = out + ((size_t)b * Tt + r2g) * Hh + 2 * tig;
#pragma unroll
    for (int nt = 0; nt < 8; nt++) {
        *(float2*)(o1 + 8 * nt) = make_float2(o[nt][0] * inv0, o[nt][1] * inv0);
        *(float2*)(o2 + 8 * nt) = make_float2(o[nt][2] * inv1, o[nt][3] * inv1);
    }
}

// ---------------------------------------------------------------------------
// Harness entry
// ---------------------------------------------------------------------------
extern "C" void kernel_launch(void* const* d_in, const int* in_sizes, int n_in,
                              void* d_out, int out_size)
{
    const float* x  = (const float*)d_in[0];
    const float* Wk = (const float*)d_in[1];
    const float* Wq = (const float*)d_in[2];
    const float* Wv = (const float*)d_in[3];
    float* out = (float*)d_out;

    cudaFuncSetAttribute(proj_tc, cudaFuncAttributeMaxDynamicSharedMemorySize, PJ_SMEM);
    cudaFuncSetAttribute(attn_tc, cudaFuncAttributeMaxDynamicSharedMemorySize, AT_SMEM);

    prep_w<<<768, 256>>>(Wk, Wq, Wv);
    proj_tc<<<BT / 128, 256, PJ_SMEM>>>(x);
    attn_tc<<<dim3(Tt / 128, Bb), 256, AT_SMEM>>>(out);
}

// round 8
// speedup vs baseline: 5.2723x; 1.1917x over previous
#include <cuda_runtime.h>
#include <cuda_fp16.h>
#include <cstdint>

// Problem constants
#define Bb 32
#define Tt 2048
#define Cc 1024
#define Hh 64
#define BT (Bb * Tt)

// 0.125 (= H^-0.5) * log2(e): scores computed directly in base-2 domain
#define QSCALE 0.180336880111227f

// Scratch (__device__ globals; no allocation allowed)
__device__ __half g_Wh[(size_t)Cc * 192];     // [k][n]  n: 0..63 K, 64..127 Q, 128..191 V
__device__ __half g_q[(size_t)BT * Hh];
__device__ __half g_k[(size_t)BT * Hh];
__device__ __half g_v[(size_t)BT * Hh];

// ---------------------------------------------------------------------------
// Helpers
// ---------------------------------------------------------------------------
__device__ __forceinline__ float ex2f(float x) {
    float r;
    asm("ex2.approx.f32 %0, %1;" : "=f"(r) : "f"(x));
    return r;
}

__device__ __forceinline__ uint32_t pk(float a, float b) {
    __half2 h = __floats2half2_rn(a, b);
    return *(uint32_t*)&h;
}

__device__ __forceinline__ uint32_t smem_u32(const void* p) {
    uint32_t a;
    asm("{ .reg .u64 t; cvta.to.shared.u64 t, %1; cvt.u32.u64 %0, t; }" : "=r"(a) : "l"(p));
    return a;
}

#define LDSM4(r, addr) \
    asm volatile("ldmatrix.sync.aligned.m8n8.x4.shared.b16 {%0,%1,%2,%3}, [%4];" \
        : "=r"((r)[0]), "=r"((r)[1]), "=r"((r)[2]), "=r"((r)[3]) : "r"(addr))
#define LDSM4T(r, addr) \
    asm volatile("ldmatrix.sync.aligned.m8n8.x4.trans.shared.b16 {%0,%1,%2,%3}, [%4];" \
        : "=r"((r)[0]), "=r"((r)[1]), "=r"((r)[2]), "=r"((r)[3]) : "r"(addr))
#define MMAH(d, a, b0_, b1_) \
    asm volatile("mma.sync.aligned.m16n8k16.row.col.f32.f16.f16.f32 " \
        "{%0,%1,%2,%3}, {%4,%5,%6,%7}, {%8,%9}, {%0,%1,%2,%3};" \
        : "+f"((d)[0]), "+f"((d)[1]), "+f"((d)[2]), "+f"((d)[3]) \
        : "r"((a)[0]), "r"((a)[1]), "r"((a)[2]), "r"((a)[3]), "r"(b0_), "r"(b1_))
#define CP_ASYNC16(dst, src) \
    asm volatile("cp.async.cg.shared.global [%0], [%1], 16;" :: "r"(dst), "l"(src))
#define CP_COMMIT() asm volatile("cp.async.commit_group;" ::: "memory")
#define CP_WAIT(n)  asm volatile("cp.async.wait_group %0;" :: "n"(n) : "memory")

// ---------------------------------------------------------------------------
// Prep: W -> fp16, Q scale folded, layout [k=1024][n=192]
// ---------------------------------------------------------------------------
__global__ __launch_bounds__(256) void prep_w(
    const float* __restrict__ Wk, const float* __restrict__ Wq, const float* __restrict__ Wv)
{
    const int idx = blockIdx.x * 256 + threadIdx.x;
    const int k = idx / 192, n = idx % 192;
    float f;
    if (n < 64)       f = Wk[k * 64 + n];
    else if (n < 128) f = Wq[k * 64 + (n - 64)] * QSCALE;
    else              f = Wv[k * 64 + (n - 128)];
    g_Wh[idx] = __float2half_rn(f);
}

// ---------------------------------------------------------------------------
// Projection GEMM, fp16 single-term, fully pipelined (unchanged from R7).
// ---------------------------------------------------------------------------
#define SB_OFF   32768
#define SB_BUF   25600
#define BSTRIDE  400
#define PJ_SMEM  83968

#define LDG_X(C0) do { \
    const float* _xs = x + (size_t)row0 * Cc + (C0) + (tid & 15) * 4; \
    _Pragma("unroll") for (int _i = 0; _i < 8; _i++) \
        xr[_i] = *(const float4*)(_xs + (size_t)(_i * 16 + (tid >> 4)) * Cc); \
} while (0)

#define CONVERT_X(P) do { \
    _Pragma("unroll") for (int _i = 0; _i < 8; _i++) { \
        const int _r = _i * 16 + (tid >> 4); \
        const int _c4 = tid & 15; \
        uint2 _hv; \
        _hv.x = pk(xr[_i].x, xr[_i].y); \
        _hv.y = pk(xr[_i].z, xr[_i].w); \
        const uint32_t _off = (uint32_t)(_r * 128 + (((_c4 >> 1) ^ (_r & 7)) << 4) + (_c4 & 1) * 8); \
        *(uint2*)(smp + (P) * 16384 + _off) = _hv; \
    } \
} while (0)

#define W_LOAD(C) do { \
    const uint32_t _bw = sb + SB_OFF + ((C) & 1) * SB_BUF; \
    _Pragma("unroll") for (int _i = 0; _i < 6; _i++) { \
        const int _u = _i * 256 + tid; \
        const int _r = _u / 24, _cg = _u % 24; \
        CP_ASYNC16(_bw + _r * BSTRIDE + _cg * 16, \
                   (const char*)(g_Wh + (size_t)((C) * 64 + _r) * 192 + _cg * 8)); \
    } \
    CP_COMMIT(); \
} while (0)

__global__ __launch_bounds__(256) void proj_tc(const float* __restrict__ x)
{
    extern __shared__ char smp[];
    const uint32_t sb = smem_u32(smp);
    const int tid  = threadIdx.x;
    const int wid  = tid >> 5;
    const int lane = tid & 31;
    const int wm   = wid >> 1;
    const int wn   = wid & 1;
    const int row0 = blockIdx.x * 128;

    const int gid = lane >> 2, tig = lane & 3;
    const int lr  = lane & 7,  grp = lane >> 3;

    float acc[2][12][4];
#pragma unroll
    for (int mi = 0; mi < 2; mi++)
#pragma unroll
        for (int j = 0; j < 12; j++)
#pragma unroll
            for (int e = 0; e < 4; e++) acc[mi][j][e] = 0.f;

    int rowA[2];
#pragma unroll
    for (int mi = 0; mi < 2; mi++) rowA[mi] = wm * 32 + mi * 16 + lr + (grp & 1) * 8;
    const int ac16g = grp >> 1;
    const uint32_t bofs = (uint32_t)((lr + (grp & 1) * 8) * BSTRIDE + wn * 192 + (grp >> 1) * 16);

    float4 xr[8];

    LDG_X(0);
    W_LOAD(0);
    CONVERT_X(0);
    LDG_X(64);

    for (int c = 0; c < 16; c++) {
        const int p = c & 1;
        CP_WAIT(0);
        __syncthreads();

        const uint32_t abh  = sb + p * 16384;
        const uint32_t bbuf = sb + SB_OFF + p * SB_BUF;
#pragma unroll
        for (int ks = 0; ks < 4; ks++) {
            uint32_t ah[2][4];
#pragma unroll
            for (int mi = 0; mi < 2; mi++) {
                const int c16 = 2 * ks + ac16g;
                LDSM4(ah[mi], abh + (uint32_t)(rowA[mi] * 128 + ((c16 ^ lr) << 4)));
            }
#pragma unroll
            for (int nt = 0; nt < 6; nt++) {
                uint32_t bh[4];
                LDSM4T(bh, bbuf + bofs + (uint32_t)(ks * 16 * BSTRIDE + nt * 32));
#pragma unroll
                for (int mi = 0; mi < 2; mi++) {
                    MMAH(acc[mi][2 * nt],     ah[mi], bh[0], bh[1]);
                    MMAH(acc[mi][2 * nt + 1], ah[mi], bh[2], bh[3]);
                }
            }
        }

        if (c < 15) {
            W_LOAD(c + 1);
            CONVERT_X(p ^ 1);
        }
        if (c < 14) LDG_X((c + 2) * 64);
    }

#pragma unroll
    for (int mi = 0; mi < 2; mi++) {
        const int r1 = row0 + wm * 32 + mi * 16 + gid;
        const int r2 = r1 + 8;
#pragma unroll
        for (int j = 0; j < 12; j++) {
            const int col = wn * 96 + j * 8 + tig * 2;
            __half* dst; int cc;
            if (col < 64)       { dst = g_k; cc = col; }
            else if (col < 128) { dst = g_q; cc = col - 64; }
            else                { dst = g_v; cc = col - 128; }
            *(uint32_t*)(dst + (size_t)r1 * Hh + cc) = pk(acc[mi][j][0], acc[mi][j][1]);
            *(uint32_t*)(dst + (size_t)r2 * Hh + cc) = pk(acc[mi][j][2], acc[mi][j][3]);
        }
    }
}

// ---------------------------------------------------------------------------
// Flash attention, fp16, MUFU-exp softmax, Q in registers, depth-2 cp.async
// prefetch over a 3-stage KV ring, 2 CTAs/SM, no register skew (no spills).
// ---------------------------------------------------------------------------
#define RSTRIDE 144
#define KV_OFF  18432             // Q: 128 rows x 144
#define KVBUF   18432             // K 9216 + V 9216
#define AT_SMEM 73728             // Q + 3 x KVBUF

#define LOAD_KV(J) do { \
    const int _jn = (J) * 64; \
    const uint32_t _bufn = sb + KV_OFF + ((J) % 3) * KVBUF; \
    _Pragma("unroll") for (int _i = 0; _i < 2; _i++) { \
        const int _idx = _i * 256 + tid; \
        const int _r = _idx >> 3, _cg = _idx & 7; \
        const size_t _g = (size_t)(b * Tt + _jn + _r) * Hh + _cg * 8; \
        const uint32_t _d0 = _bufn + _r * RSTRIDE + _cg * 16; \
        CP_ASYNC16(_d0,        (const char*)(g_k + _g)); \
        CP_ASYNC16(_d0 + 9216, (const char*)(g_v + _g)); \
    } \
} while (0)

__global__ __launch_bounds__(256, 2) void attn_tc(float* __restrict__ out)
{
    extern __shared__ char sma[];
    const uint32_t sb  = smem_u32(sma);
    const uint32_t sQh = sb;

    const int tid  = threadIdx.x;
    const int w    = tid >> 5;
    const int lane = tid & 31;
    const int b    = blockIdx.y;
    const int it   = (Tt / 128 - 1) - blockIdx.x;    // heaviest tiles first
    const int q0   = it * 128;
    const int jmax = 2 * it + 1;                     // >= 1

    const int gid = lane >> 2, tig = lane & 3;
    const int lr  = lane & 7,  grp = lane >> 3;

    const uint32_t aQ = (uint32_t)((16 * w + lr + (grp & 1) * 8) * RSTRIDE + (grp >> 1) * 16);
    const uint32_t aK = (uint32_t)((lr + (grp >> 1) * 8) * RSTRIDE + (grp & 1) * 16);
    const uint32_t aV = (uint32_t)((lr + (grp & 1) * 8) * RSTRIDE + (grp >> 1) * 16);

    // ---- prologue: group0 = Q, group1 = KV(0), group2 = KV(1) ----
#pragma unroll
    for (int i = 0; i < 4; i++) {
        const int idx = i * 256 + tid;
        const int r = idx >> 3, cg = idx & 7;
        CP_ASYNC16(sQh + r * RSTRIDE + cg * 16,
                   (const char*)(g_q + (size_t)(b * Tt + q0 + r) * Hh + cg * 8));
    }
    CP_COMMIT();
    LOAD_KV(0);
    CP_COMMIT();
    LOAD_KV(1);
    CP_COMMIT();

    // ---- wait for Q, pull it into registers for good ----
    CP_WAIT(2);
    __syncthreads();
    uint32_t qf[4][4];
#pragma unroll
    for (int ks = 0; ks < 4; ks++) LDSM4(qf[ks], sQh + aQ + ks * 32);

    float o[8][4];
#pragma unroll
    for (int nt = 0; nt < 8; nt++)
#pragma unroll
        for (int e = 0; e < 4; e++) o[nt][e] = 0.f;
    float m0 = -1e30f, m1 = -1e30f, l0 = 0.f, l1 = 0.f;

    const int r1g = q0 + 16 * w + gid;
    const int r2g = r1g + 8;
    const bool live_hi = true;   // warp band upper bound: q0 + 16w + 15

    for (int jt = 0; jt <= jmax; jt++) {
        // invariant: two groups outstanding; wait(1) completes the one with KV(jt)
        CP_WAIT(1);
        __syncthreads();

        // issue next prefetch (or empty commit to keep the group invariant)
        if (jt + 2 <= jmax) LOAD_KV(jt + 2);
        CP_COMMIT();

        const int j0 = jt * 64;
        if (j0 <= q0 + 16 * w + 15) {
            const uint32_t buf  = sb + KV_OFF + (jt % 3) * KVBUF;
            const uint32_t bufv = buf + 9216;

            // ---- S = Q @ K^T ----
            float s[8][4];
#pragma unroll
            for (int nt = 0; nt < 8; nt++)
#pragma unroll
                for (int e = 0; e < 4; e++) s[nt][e] = 0.f;
#pragma unroll
            for (int ks = 0; ks < 4; ks++) {
#pragma unroll
                for (int np = 0; np < 4; np++) {
                    uint32_t bh[4];
                    LDSM4(bh, buf + aK + np * (16 * RSTRIDE) + ks * 32);
                    MMAH(s[2 * np],     qf[ks], bh[0], bh[1]);
                    MMAH(s[2 * np + 1], qf[ks], bh[2], bh[3]);
                }
            }

            // ---- causal mask ----
            if (j0 + 63 > q0 + 16 * w) {
#pragma unroll
                for (int nt = 0; nt < 8; nt++) {
                    const int cb = j0 + 8 * nt + 2 * tig;
                    if (cb     > r1g) s[nt][0] = -1e30f;
                    if (cb + 1 > r1g) s[nt][1] = -1e30f;
                    if (cb     > r2g) s[nt][2] = -1e30f;
                    if (cb + 1 > r2g) s[nt][3] = -1e30f;
                }
            }

            // ---- online softmax: MUFU ex2, no clamps needed ----
            float mx0 = s[0][0], mx1 = s[0][2];
#pragma unroll
            for (int nt = 0; nt < 8; nt++) {
                mx0 = fmaxf(mx0, fmaxf(s[nt][0], s[nt][1]));
                mx1 = fmaxf(mx1, fmaxf(s[nt][2], s[nt][3]));
            }
            mx0 = fmaxf(mx0, __shfl_xor_sync(0xffffffffu, mx0, 1));
            mx0 = fmaxf(mx0, __shfl_xor_sync(0xffffffffu, mx0, 2));
            mx1 = fmaxf(mx1, __shfl_xor_sync(0xffffffffu, mx1, 1));
            mx1 = fmaxf(mx1, __shfl_xor_sync(0xffffffffu, mx1, 2));
            const float mn0 = fmaxf(m0, mx0), mn1 = fmaxf(m1, mx1);
            const float a0 = ex2f(m0 - mn0);
            const float a1 = ex2f(m1 - mn1);
            float sm0 = 0.f, sm1 = 0.f;
#pragma unroll
            for (int nt = 0; nt < 8; nt++) {
                s[nt][0] = ex2f(s[nt][0] - mn0);
                s[nt][1] = ex2f(s[nt][1] - mn0);
                s[nt][2] = ex2f(s[nt][2] - mn1);
                s[nt][3] = ex2f(s[nt][3] - mn1);
                sm0 += s[nt][0] + s[nt][1];
                sm1 += s[nt][2] + s[nt][3];
            }
            sm0 += __shfl_xor_sync(0xffffffffu, sm0, 1);
            sm0 += __shfl_xor_sync(0xffffffffu, sm0, 2);
            sm1 += __shfl_xor_sync(0xffffffffu, sm1, 1);
            sm1 += __shfl_xor_sync(0xffffffffu, sm1, 2);
            l0 = l0 * a0 + sm0;
            l1 = l1 * a1 + sm1;
            m0 = mn0; m1 = mn1;
#pragma unroll
            for (int nt = 0; nt < 8; nt++) {
                o[nt][0] *= a0; o[nt][1] *= a0;
                o[nt][2] *= a1; o[nt][3] *= a1;
            }

            // ---- O += P @ V ----
#pragma unroll
            for (int kt = 0; kt < 4; kt++) {
                uint32_t ah[4];
                ah[0] = pk(s[2 * kt][0],     s[2 * kt][1]);
                ah[1] = pk(s[2 * kt][2],     s[2 * kt][3]);
                ah[2] = pk(s[2 * kt + 1][0], s[2 * kt + 1][1]);
                ah[3] = pk(s[2 * kt + 1][2], s[2 * kt + 1][3]);
#pragma unroll
                for (int nh = 0; nh < 4; nh++) {
                    uint32_t bh[4];
                    LDSM4T(bh, bufv + aV + kt * (16 * RSTRIDE) + nh * 32);
                    MMAH(o[2 * nh],     ah, bh[0], bh[1]);
                    MMAH(o[2 * nh + 1], ah, bh[2], bh[3]);
                }
            }
        }
    }

    // ---- normalize + write ----
    const float inv0 = 1.f / l0, inv1 = 1.f / l1;
    float* o1 = out + ((size_t)b * Tt + r1g) * Hh + 2 * tig;
    float* o2 = out + ((size_t)b * Tt + r2g) * Hh + 2 * tig;
#pragma unroll
    for (int nt = 0; nt < 8; nt++) {
        *(float2*)(o1 + 8 * nt) = make_float2(o[nt][0] * inv0, o[nt][1] * inv0);
        *(float2*)(o2 + 8 * nt) = make_float2(o[nt][2] * inv1, o[nt][3] * inv1);
    }
}

// ---------------------------------------------------------------------------
// Harness entry
// ---------------------------------------------------------------------------
extern "C" void kernel_launch(void* const* d_in, const int* in_sizes, int n_in,
                              void* d_out, int out_size)
{
    const float* x  = (const float*)d_in[0];
    const float* Wk = (const float*)d_in[1];
    const float* Wq = (const float*)d_in[2];
    const float* Wv = (const float*)d_in[3];
    float* out = (float*)d_out;

    cudaFuncSetAttribute(proj_tc, cudaFuncAttributeMaxDynamicSharedMemorySize, PJ_SMEM);
    cudaFuncSetAttribute(attn_tc, cudaFuncAttributeMaxDynamicSharedMemorySize, AT_SMEM);

    prep_w<<<768, 256>>>(Wk, Wq, Wv);
    proj_tc<<<BT / 128, 256, PJ_SMEM>>>(x);
    attn_tc<<<dim3(Tt / 128, Bb), 256, AT_SMEM>>>(out);
}